// round 7
// baseline (speedup 1.0000x reference)
#include <cuda_runtime.h>
#include <cuda_bf16.h>
#include <cstdint>

// Problem constants
constexpr int B_  = 2;
constexpr int T_  = 2048;
constexpr int C_  = 1024;
constexpr int H_  = 16;
constexpr int D_  = 64;
constexpr int C3_ = 3 * C_;   // 3072
constexpr int M_  = B_ * T_;  // 4096

// Scratch (allocation-free rule: __device__ globals)
__device__ __nv_bfloat16 g_x_hi  [(size_t)M_  * C_];
__device__ __nv_bfloat16 g_x_lo  [(size_t)M_  * C_];
__device__ __nv_bfloat16 g_wa_hi [(size_t)C3_ * C_];
__device__ __nv_bfloat16 g_wa_lo [(size_t)C3_ * C_];
__device__ __nv_bfloat16 g_wp_hi [(size_t)C_  * C_];
__device__ __nv_bfloat16 g_wp_lo [(size_t)C_  * C_];
__device__ __nv_bfloat16 g_qkv_hi[(size_t)M_  * C3_];
__device__ __nv_bfloat16 g_qkv_lo[(size_t)M_  * C3_];
__device__ __nv_bfloat16 g_y_hi  [(size_t)M_  * C_];
__device__ __nv_bfloat16 g_y_lo  [(size_t)M_  * C_];

// ---------------------------------------------------------------------------
// Baseline-PTX helpers (sm_80+ only)
// ---------------------------------------------------------------------------
__device__ __forceinline__ uint32_t smem_u32(const void* p) {
    uint32_t a;
    asm("{ .reg .u64 t; cvta.to.shared.u64 t, %1; cvt.u32.u64 %0, t; }"
        : "=r"(a) : "l"(p));
    return a;
}
__device__ __forceinline__ void cp_async16(uint32_t saddr, const void* gaddr) {
    asm volatile("cp.async.cg.shared.global [%0], [%1], 16;"
                 :: "r"(saddr), "l"(gaddr) : "memory");
}
__device__ __forceinline__ void cp_commit() {
    asm volatile("cp.async.commit_group;" ::: "memory");
}
template <int N>
__device__ __forceinline__ void cp_wait() {
    asm volatile("cp.async.wait_group %0;" :: "n"(N) : "memory");
}
__device__ __forceinline__ void ldsm_x4(uint32_t& r0, uint32_t& r1,
                                        uint32_t& r2, uint32_t& r3, uint32_t addr) {
    asm volatile("ldmatrix.sync.aligned.m8n8.x4.shared.b16 {%0,%1,%2,%3}, [%4];"
                 : "=r"(r0), "=r"(r1), "=r"(r2), "=r"(r3) : "r"(addr));
}
__device__ __forceinline__ void ldsm_x4_t(uint32_t& r0, uint32_t& r1,
                                          uint32_t& r2, uint32_t& r3, uint32_t addr) {
    asm volatile("ldmatrix.sync.aligned.m8n8.x4.trans.shared.b16 {%0,%1,%2,%3}, [%4];"
                 : "=r"(r0), "=r"(r1), "=r"(r2), "=r"(r3) : "r"(addr));
}
__device__ __forceinline__ void mma16816(float* d, const uint32_t* a, const uint32_t* b) {
    asm volatile(
        "mma.sync.aligned.m16n8k16.row.col.f32.bf16.bf16.f32 "
        "{%0,%1,%2,%3}, {%4,%5,%6,%7}, {%8,%9}, {%0,%1,%2,%3};"
        : "+f"(d[0]), "+f"(d[1]), "+f"(d[2]), "+f"(d[3])
        : "r"(a[0]), "r"(a[1]), "r"(a[2]), "r"(a[3]), "r"(b[0]), "r"(b[1]));
}
__device__ __forceinline__ void split2(float v0, float v1, uint32_t& hi, uint32_t& lo) {
    __nv_bfloat16 h0 = __float2bfloat16(v0), h1 = __float2bfloat16(v1);
    __nv_bfloat16 l0 = __float2bfloat16(v0 - __bfloat162float(h0));
    __nv_bfloat16 l1 = __float2bfloat16(v1 - __bfloat162float(h1));
    __nv_bfloat162 Hv(h0, h1), Lv(l0, l1);
    hi = *(uint32_t*)&Hv; lo = *(uint32_t*)&Lv;
}

// ---------------------------------------------------------------------------
// fp32 -> bf16 hi/lo split
// ---------------------------------------------------------------------------
__global__ __launch_bounds__(256)
void split_bf16(const float* __restrict__ in, __nv_bfloat16* __restrict__ hi,
                __nv_bfloat16* __restrict__ lo, int n4)
{
    int i = blockIdx.x * blockDim.x + threadIdx.x;
    if (i >= n4) return;
    float4 v = ((const float4*)in)[i];
    uint32_t h01, l01, h23, l23;
    split2(v.x, v.y, h01, l01);
    split2(v.z, v.w, h23, l23);
    ((uint32_t*)hi)[2 * i + 0] = h01; ((uint32_t*)hi)[2 * i + 1] = h23;
    ((uint32_t*)lo)[2 * i + 0] = l01; ((uint32_t*)lo)[2 * i + 1] = l23;
}

// ---------------------------------------------------------------------------
// HMMA GEMM (NT): 512 threads, 16 warps (4x4), warp tile 32x32, BK=32,
// 5-buffer cp.async ring. All stage LDSMs issued before MMAs (overlap).
// ---------------------------------------------------------------------------
constexpr int BK_   = 32;
constexpr int SKS_  = 40;
constexpr int MAT_E = 128 * SKS_;
constexpr int STAGE_E = 4 * MAT_E;               // Ah, Al, Bh, Bl
constexpr int NBUF_G = 5;
constexpr int GEMM_SMEM = NBUF_G * STAGE_E * 2;  // 204800 B

__device__ __forceinline__ void stage_loads(uint32_t sbuf,
    const __nv_bfloat16* Ahi, const __nv_bfloat16* Alo,
    const __nv_bfloat16* Bhi, const __nv_bfloat16* Blo,
    int bm, int bn, int k0, int K, int tid)
{
    const __nv_bfloat16* srcs[4] = { Ahi, Alo, Bhi, Blo };
    const int r0s[4] = { bm, bm, bn, bn };
    const int row = tid >> 2;
    const int cb  = (tid & 3) * 8;
    const uint32_t so = (row * SKS_ + cb) * 2;
#pragma unroll
    for (int m = 0; m < 4; m++) {
        const void* g = srcs[m] + (size_t)(r0s[m] + row) * K + k0 + cb;
        cp_async16(sbuf + m * MAT_E * 2 + so, g);
    }
    cp_commit();
}

template <int OUTMODE>
__global__ __launch_bounds__(512, 1)
void gemm_mma(const __nv_bfloat16* __restrict__ Ahi, const __nv_bfloat16* __restrict__ Alo,
              const __nv_bfloat16* __restrict__ Bhi, const __nv_bfloat16* __restrict__ Blo,
              const float* __restrict__ bias, float* __restrict__ Cf,
              __nv_bfloat16* __restrict__ Chi, __nv_bfloat16* __restrict__ Clo,
              int M, int N, int K)
{
    extern __shared__ __align__(128) __nv_bfloat16 smem[];
    const int tid  = threadIdx.x;
    const int wid  = tid >> 5;
    const int lane = tid & 31;
    const int wm   = wid >> 2;
    const int wn   = wid & 3;
    const int bm   = blockIdx.y * 128;
    const int bn   = blockIdx.x * 128;
    const uint32_t sbase = smem_u32(smem);

    float acc[2][4][4];
#pragma unroll
    for (int i = 0; i < 2; i++)
#pragma unroll
        for (int j = 0; j < 4; j++)
#pragma unroll
            for (int r = 0; r < 4; r++) acc[i][j][r] = 0.f;

    const int a_row = wm * 32 + (lane & 15);
    const int a_col = (lane >> 4) * 8;
    const int b_row = wn * 32 + ((lane >> 4) & 1) * 8 + (lane & 7);
    const int b_col = ((lane >> 3) & 1) * 8;

    const int S = K / BK_;   // 32

#pragma unroll
    for (int p = 0; p < 4; p++)
        stage_loads(sbase + p * STAGE_E * 2, Ahi, Alo, Bhi, Blo,
                    bm, bn, p * BK_, K, tid);

    int buf = 0, nbuf = 4 % NBUF_G;
    for (int s = 0; s < S; s++) {
        cp_wait<3>();
        __syncthreads();

        const uint32_t sb  = sbase + buf * STAGE_E * 2;
        const uint32_t sAh = sb;
        const uint32_t sAl = sb + MAT_E * 2;
        const uint32_t sBh = sb + 2 * MAT_E * 2;
        const uint32_t sBl = sb + 3 * MAT_E * 2;

        // Issue ALL of this stage's LDSMs first (both ks slots) so the
        // crossbar drains underneath the MMA phase.
        uint32_t ah[2][2][4], al[2][2][4], bh[2][2][4], bl[2][2][4];
#pragma unroll
        for (int ks = 0; ks < 2; ks++) {
            const int ac = a_col + ks * 16;
            const int bc = b_col + ks * 16;
#pragma unroll
            for (int mt = 0; mt < 2; mt++) {
                uint32_t ra = ((a_row + mt * 16) * SKS_ + ac) * 2;
                ldsm_x4(ah[ks][mt][0], ah[ks][mt][1], ah[ks][mt][2], ah[ks][mt][3], sAh + ra);
                ldsm_x4(al[ks][mt][0], al[ks][mt][1], al[ks][mt][2], al[ks][mt][3], sAl + ra);
            }
#pragma unroll
            for (int np = 0; np < 2; np++) {
                uint32_t rb = ((b_row + np * 16) * SKS_ + bc) * 2;
                ldsm_x4(bh[ks][np][0], bh[ks][np][1], bh[ks][np][2], bh[ks][np][3], sBh + rb);
                ldsm_x4(bl[ks][np][0], bl[ks][np][1], bl[ks][np][2], bl[ks][np][3], sBl + rb);
            }
        }

        // Next stage's global prefetch issues while fragments are in flight.
        if (s + 4 < S)
            stage_loads(sbase + nbuf * STAGE_E * 2, Ahi, Alo, Bhi, Blo,
                        bm, bn, (s + 4) * BK_, K, tid);
        else
            cp_commit();

#pragma unroll
        for (int ks = 0; ks < 2; ks++)
#pragma unroll
            for (int mt = 0; mt < 2; mt++)
#pragma unroll
                for (int nt = 0; nt < 4; nt++) {
                    const uint32_t* bhp = &bh[ks][nt >> 1][(nt & 1) * 2];
                    const uint32_t* blp = &bl[ks][nt >> 1][(nt & 1) * 2];
                    mma16816(acc[mt][nt], ah[ks][mt], bhp);
                    mma16816(acc[mt][nt], ah[ks][mt], blp);
                    mma16816(acc[mt][nt], al[ks][mt], bhp);
                }

        if (++buf == NBUF_G)  buf = 0;
        if (++nbuf == NBUF_G) nbuf = 0;
    }

    const int er = lane >> 2;
    const int ec = (lane & 3) * 2;
#pragma unroll
    for (int mt = 0; mt < 2; mt++) {
        const int row0 = bm + wm * 32 + mt * 16 + er;
#pragma unroll
        for (int nt = 0; nt < 4; nt++) {
            const int col = bn + wn * 32 + nt * 8 + ec;
            const float bx = bias[col], by = bias[col + 1];
            float v0 = acc[mt][nt][0] + bx, v1 = acc[mt][nt][1] + by;
            float v2 = acc[mt][nt][2] + bx, v3 = acc[mt][nt][3] + by;
            if (OUTMODE == 0) {
                *(float2*)(Cf + (size_t)row0 * N + col)       = make_float2(v0, v1);
                *(float2*)(Cf + (size_t)(row0 + 8) * N + col) = make_float2(v2, v3);
            } else {
                uint32_t uh, ul;
                split2(v0, v1, uh, ul);
                *(uint32_t*)(Chi + (size_t)row0 * N + col) = uh;
                *(uint32_t*)(Clo + (size_t)row0 * N + col) = ul;
                split2(v2, v3, uh, ul);
                *(uint32_t*)(Chi + (size_t)(row0 + 8) * N + col) = uh;
                *(uint32_t*)(Clo + (size_t)(row0 + 8) * N + col) = ul;
            }
        }
    }
}

// ---------------------------------------------------------------------------
// HMMA causal flash attention, 3-buffer KV ring, fragment-pipelined.
// CTA: 128 q-rows x (b,h). 8 warps x 16 rows. 64-key blocks.
// ---------------------------------------------------------------------------
constexpr int SKA_    = 72;
constexpr int QTILE_E = 128 * SKA_;
constexpr int KTILE_E = 64 * SKA_;
constexpr int ATT_STAGE_E = 4 * KTILE_E;
constexpr int NBUF_A  = 3;
constexpr int ATT_SMEM = (2 * QTILE_E + NBUF_A * ATT_STAGE_E) * 2;  // 147456 B

__device__ __forceinline__ void stage_kv(uint32_t sbuf,
    const __nv_bfloat16* qh, const __nv_bfloat16* ql,
    size_t bbase, int colK, int colV, int j0, int tid)
{
#pragma unroll
    for (int it = 0; it < 2; it++) {
        int s   = tid + it * 256;
        int row = s >> 3;
        int ch  = (s & 7) * 8;
        size_t g = bbase + (size_t)(j0 + row) * C3_;
        uint32_t so = (row * SKA_ + ch) * 2;
        cp_async16(sbuf + 0 * KTILE_E * 2 + so, qh + g + colK + ch);
        cp_async16(sbuf + 1 * KTILE_E * 2 + so, ql + g + colK + ch);
        cp_async16(sbuf + 2 * KTILE_E * 2 + so, qh + g + colV + ch);
        cp_async16(sbuf + 3 * KTILE_E * 2 + so, ql + g + colV + ch);
    }
}

__global__ __launch_bounds__(256, 1)
void attn_mma(const __nv_bfloat16* __restrict__ qvh, const __nv_bfloat16* __restrict__ qvl,
              __nv_bfloat16* __restrict__ yh, __nv_bfloat16* __restrict__ yl)
{
    extern __shared__ __align__(128) __nv_bfloat16 asm_[];
    const int tid  = threadIdx.x;
    const int wid  = tid >> 5;
    const int lane = tid & 31;
    const int qb = (int)gridDim.x - 1 - (int)blockIdx.x;
    const int bh = blockIdx.y;
    const int b  = bh >> 4;
    const int h  = bh & 15;
    const int q0 = qb * 128;
    const size_t bbase = (size_t)b * T_ * C3_;
    const int colQ = h * D_, colK = C_ + h * D_, colV = 2 * C_ + h * D_;

    const uint32_t sQh = smem_u32(asm_);
    const uint32_t sQl = sQh + QTILE_E * 2;
    const uint32_t sSt = sQl + QTILE_E * 2;

    const int nb = 2 * qb + 2;

#pragma unroll
    for (int it = 0; it < 4; it++) {
        int s   = tid + it * 256;
        int row = s >> 3;
        int ch  = (s & 7) * 8;
        size_t g = bbase + (size_t)(q0 + row) * C3_ + colQ + ch;
        uint32_t so = (row * SKA_ + ch) * 2;
        cp_async16(sQh + so, qvh + g);
        cp_async16(sQl + so, qvl + g);
    }
    stage_kv(sSt, qvh, qvl, bbase, colK, colV, 0, tid);
    cp_commit();
    if (1 < nb) stage_kv(sSt + ATT_STAGE_E * 2, qvh, qvl, bbase, colK, colV, 64, tid);
    cp_commit();

    uint32_t aqh[4][4], aql[4][4];
    float oc[8][4];
#pragma unroll
    for (int i = 0; i < 8; i++)
#pragma unroll
        for (int j = 0; j < 4; j++) oc[i][j] = 0.f;
    float mrow[2] = { -1e30f, -1e30f };
    float lrow[2] = { 0.f, 0.f };

    const float scl = 0.125f * 1.4426950408889634f;
    const int wrow0 = q0 + 16 * wid;

    int buf = 0, nbufi = 2;
    for (int j = 0; j < nb; j++) {
        cp_wait<1>();
        __syncthreads();

        if (j == 0) {
#pragma unroll
            for (int kc = 0; kc < 4; kc++) {
                uint32_t ra = (((16 * wid) + (lane & 15)) * SKA_
                               + (lane >> 4) * 8 + kc * 16) * 2;
                ldsm_x4(aqh[kc][0], aqh[kc][1], aqh[kc][2], aqh[kc][3], sQh + ra);
                ldsm_x4(aql[kc][0], aql[kc][1], aql[kc][2], aql[kc][3], sQl + ra);
            }
        }

        if (j + 2 < nb)
            stage_kv(sSt + nbufi * ATT_STAGE_E * 2, qvh, qvl,
                     bbase, colK, colV, (j + 2) * 64, tid);
        cp_commit();

        const int j0 = j * 64;
        if (j0 <= wrow0 + 15) {
            const uint32_t sb  = sSt + buf * ATT_STAGE_E * 2;
            const uint32_t sKh = sb;
            const uint32_t sKl = sb + 1 * KTILE_E * 2;
            const uint32_t sVh = sb + 2 * KTILE_E * 2;
            const uint32_t sVl = sb + 3 * KTILE_E * 2;

            float sc[8][4];
#pragma unroll
            for (int i = 0; i < 8; i++)
#pragma unroll
                for (int e = 0; e < 4; e++) sc[i][e] = 0.f;

            // ---- S = Q K^T, K-fragments double-buffered across kc ----
            const int kb_r = ((lane >> 4) & 1) * 8 + (lane & 7);
            const int kb_c = ((lane >> 3) & 1) * 8;
            uint32_t kbh[2][4][4], kbl[2][4][4];
#pragma unroll
            for (int g = 0; g < 4; g++) {
                uint32_t off = ((g * 16 + kb_r) * SKA_ + kb_c) * 2;
                ldsm_x4(kbh[0][g][0], kbh[0][g][1], kbh[0][g][2], kbh[0][g][3], sKh + off);
                ldsm_x4(kbl[0][g][0], kbl[0][g][1], kbl[0][g][2], kbl[0][g][3], sKl + off);
            }
#pragma unroll
            for (int kc = 0; kc < 4; kc++) {
                const int cur = kc & 1, nxt = cur ^ 1;
                if (kc < 3) {
#pragma unroll
                    for (int g = 0; g < 4; g++) {
                        uint32_t off = ((g * 16 + kb_r) * SKA_ + kb_c + (kc + 1) * 16) * 2;
                        ldsm_x4(kbh[nxt][g][0], kbh[nxt][g][1], kbh[nxt][g][2], kbh[nxt][g][3], sKh + off);
                        ldsm_x4(kbl[nxt][g][0], kbl[nxt][g][1], kbl[nxt][g][2], kbl[nxt][g][3], sKl + off);
                    }
                }
#pragma unroll
                for (int nt = 0; nt < 8; nt++) {
                    const uint32_t* bp_h = &kbh[cur][nt >> 1][(nt & 1) * 2];
                    const uint32_t* bp_l = &kbl[cur][nt >> 1][(nt & 1) * 2];
                    mma16816(sc[nt], aqh[kc], bp_h);
                    mma16816(sc[nt], aqh[kc], bp_l);
                    mma16816(sc[nt], aql[kc], bp_h);
                }
            }

            const bool anymask = (j0 + 63 > wrow0);
            const int r0g = wrow0 + (lane >> 2);
#pragma unroll
            for (int nt = 0; nt < 8; nt++)
#pragma unroll
                for (int e = 0; e < 4; e++) {
                    float v = sc[nt][e] * scl;
                    if (anymask) {
                        int key = j0 + nt * 8 + (lane & 3) * 2 + (e & 1);
                        int row = r0g + (e >> 1) * 8;
                        if (key > row) v = -1e30f;
                    }
                    sc[nt][e] = v;
                }

#pragma unroll
            for (int rr = 0; rr < 2; rr++) {
                float mx = -1e30f;
#pragma unroll
                for (int nt = 0; nt < 8; nt++)
                    mx = fmaxf(mx, fmaxf(sc[nt][2 * rr], sc[nt][2 * rr + 1]));
                mx = fmaxf(mx, __shfl_xor_sync(0xffffffffu, mx, 1));
                mx = fmaxf(mx, __shfl_xor_sync(0xffffffffu, mx, 2));
                float mnew = fmaxf(mrow[rr], mx);
                float al   = exp2f(mrow[rr] - mnew);
                mrow[rr] = mnew;
                float rs = 0.f;
#pragma unroll
                for (int nt = 0; nt < 8; nt++) {
                    float p0 = exp2f(sc[nt][2 * rr]     - mnew);
                    float p1 = exp2f(sc[nt][2 * rr + 1] - mnew);
                    sc[nt][2 * rr] = p0; sc[nt][2 * rr + 1] = p1;
                    rs += p0 + p1;
                }
                rs += __shfl_xor_sync(0xffffffffu, rs, 1);
                rs += __shfl_xor_sync(0xffffffffu, rs, 2);
                lrow[rr] = lrow[rr] * al + rs;
#pragma unroll
                for (int nd = 0; nd < 8; nd++) {
                    oc[nd][2 * rr]     *= al;
                    oc[nd][2 * rr + 1] *= al;
                }
            }

            // ---- O += P V, V-fragments double-buffered across nd2 ----
#pragma unroll
            for (int t = 0; t < 4; t++) {
                uint32_t ph[4], pl[4];
                split2(sc[2 * t][0],     sc[2 * t][1],     ph[0], pl[0]);
                split2(sc[2 * t][2],     sc[2 * t][3],     ph[1], pl[1]);
                split2(sc[2 * t + 1][0], sc[2 * t + 1][1], ph[2], pl[2]);
                split2(sc[2 * t + 1][2], sc[2 * t + 1][3], ph[3], pl[3]);
                const int vkey = 16 * t + ((lane >> 3) & 1) * 8 + (lane & 7);
                const int vcb  = (lane >> 4) * 8;
                uint32_t vfh[2][4], vfl[2][4];
                {
                    uint32_t off = (vkey * SKA_ + vcb) * 2;
                    ldsm_x4_t(vfh[0][0], vfh[0][1], vfh[0][2], vfh[0][3], sVh + off);
                    ldsm_x4_t(vfl[0][0], vfl[0][1], vfl[0][2], vfl[0][3], sVl + off);
                }
#pragma unroll
                for (int nd2 = 0; nd2 < 4; nd2++) {
                    const int cur = nd2 & 1, nxt = cur ^ 1;
                    if (nd2 < 3) {
                        uint32_t off = (vkey * SKA_ + (nd2 + 1) * 16 + vcb) * 2;
                        ldsm_x4_t(vfh[nxt][0], vfh[nxt][1], vfh[nxt][2], vfh[nxt][3], sVh + off);
                        ldsm_x4_t(vfl[nxt][0], vfl[nxt][1], vfl[nxt][2], vfl[nxt][3], sVl + off);
                    }
                    mma16816(oc[2 * nd2],     ph, &vfh[cur][0]);
                    mma16816(oc[2 * nd2],     ph, &vfl[cur][0]);
                    mma16816(oc[2 * nd2],     pl, &vfh[cur][0]);
                    mma16816(oc[2 * nd2 + 1], ph, &vfh[cur][2]);
                    mma16816(oc[2 * nd2 + 1], ph, &vfl[cur][2]);
                    mma16816(oc[2 * nd2 + 1], pl, &vfh[cur][2]);
                }
            }
        }
        if (++buf == NBUF_A)   buf = 0;
        if (++nbufi == NBUF_A) nbufi = 0;
    }

    const float inv0 = 1.0f / lrow[0];
    const float inv1 = 1.0f / lrow[1];
    const int gr0 = wrow0 + (lane >> 2);
    const int gr1 = gr0 + 8;
    const int colb = h * D_ + (lane & 3) * 2;
#pragma unroll
    for (int nd = 0; nd < 8; nd++) {
        const int col = colb + nd * 8;
        uint32_t uh, ul;
        split2(oc[nd][0] * inv0, oc[nd][1] * inv0, uh, ul);
        *(uint32_t*)(yh + ((size_t)b * T_ + gr0) * C_ + col) = uh;
        *(uint32_t*)(yl + ((size_t)b * T_ + gr0) * C_ + col) = ul;
        split2(oc[nd][2] * inv1, oc[nd][3] * inv1, uh, ul);
        *(uint32_t*)(yh + ((size_t)b * T_ + gr1) * C_ + col) = uh;
        *(uint32_t*)(yl + ((size_t)b * T_ + gr1) * C_ + col) = ul;
    }
}

// ---------------------------------------------------------------------------
extern "C" void kernel_launch(void* const* d_in, const int* in_sizes, int n_in,
                              void* d_out, int out_size)
{
    const float* x      = (const float*)d_in[0];
    const float* w_attn = (const float*)d_in[1];
    const float* b_attn = (const float*)d_in[2];
    const float* w_proj = (const float*)d_in[3];
    const float* b_proj = (const float*)d_in[4];
    float* out = (float*)d_out;

    __nv_bfloat16 *xh, *xl, *wah, *wal, *wph, *wpl, *qh, *ql, *yh, *yl;
    cudaGetSymbolAddress((void**)&xh,  g_x_hi);
    cudaGetSymbolAddress((void**)&xl,  g_x_lo);
    cudaGetSymbolAddress((void**)&wah, g_wa_hi);
    cudaGetSymbolAddress((void**)&wal, g_wa_lo);
    cudaGetSymbolAddress((void**)&wph, g_wp_hi);
    cudaGetSymbolAddress((void**)&wpl, g_wp_lo);
    cudaGetSymbolAddress((void**)&qh,  g_qkv_hi);
    cudaGetSymbolAddress((void**)&ql,  g_qkv_lo);
    cudaGetSymbolAddress((void**)&yh,  g_y_hi);
    cudaGetSymbolAddress((void**)&yl,  g_y_lo);

    cudaFuncSetAttribute(gemm_mma<0>, cudaFuncAttributeMaxDynamicSharedMemorySize, GEMM_SMEM);
    cudaFuncSetAttribute(gemm_mma<1>, cudaFuncAttributeMaxDynamicSharedMemorySize, GEMM_SMEM);
    cudaFuncSetAttribute(attn_mma,    cudaFuncAttributeMaxDynamicSharedMemorySize, ATT_SMEM);

    {
        int n4;
        n4 = M_ * C_ / 4;   split_bf16<<<(n4 + 255) / 256, 256>>>(x,      xh,  xl,  n4);
        n4 = C3_ * C_ / 4;  split_bf16<<<(n4 + 255) / 256, 256>>>(w_attn, wah, wal, n4);
        n4 = C_ * C_ / 4;   split_bf16<<<(n4 + 255) / 256, 256>>>(w_proj, wph, wpl, n4);
    }

    {
        dim3 grid(C3_ / 128, M_ / 128);
        gemm_mma<1><<<grid, 512, GEMM_SMEM>>>(xh, xl, wah, wal, b_attn,
                                              nullptr, qh, ql, M_, C3_, C_);
    }
    {
        dim3 grid(T_ / 128, B_ * H_);
        attn_mma<<<grid, 256, ATT_SMEM>>>(qh, ql, yh, yl);
    }
    {
        dim3 grid(C_ / 128, M_ / 128);
        gemm_mma<0><<<grid, 512, GEMM_SMEM>>>(yh, yl, wph, wpl, b_proj,
                                              out, nullptr, nullptr, M_, C_, C_);
    }
}

// round 8
// speedup vs baseline: 1.4646x; 1.4646x over previous
#include <cuda_runtime.h>
#include <cuda_fp16.h>
#include <cstdint>

// Problem constants
constexpr int B_  = 2;
constexpr int T_  = 2048;
constexpr int C_  = 1024;
constexpr int H_  = 16;
constexpr int D_  = 64;
constexpr int C3_ = 3 * C_;   // 3072
constexpr int M_  = B_ * T_;  // 4096

// Scratch (allocation-free rule: __device__ globals). fp16 hi/lo splits.
__device__ __half g_x_hi  [(size_t)M_  * C_];
__device__ __half g_x_lo  [(size_t)M_  * C_];
__device__ __half g_wa    [(size_t)C3_ * C_];   // w_attn single fp16
__device__ __half g_wp    [(size_t)C_  * C_];   // w_proj single fp16
__device__ __half g_qkv_hi[(size_t)M_  * C3_];
__device__ __half g_qkv_lo[(size_t)M_  * C3_];
__device__ __half g_y_hi  [(size_t)M_  * C_];
__device__ __half g_y_lo  [(size_t)M_  * C_];

// ---------------------------------------------------------------------------
// Baseline-PTX helpers (sm_80+ only)
// ---------------------------------------------------------------------------
__device__ __forceinline__ uint32_t smem_u32(const void* p) {
    uint32_t a;
    asm("{ .reg .u64 t; cvta.to.shared.u64 t, %1; cvt.u32.u64 %0, t; }"
        : "=r"(a) : "l"(p));
    return a;
}
__device__ __forceinline__ void cp_async16(uint32_t saddr, const void* gaddr) {
    asm volatile("cp.async.cg.shared.global [%0], [%1], 16;"
                 :: "r"(saddr), "l"(gaddr) : "memory");
}
__device__ __forceinline__ void cp_commit() {
    asm volatile("cp.async.commit_group;" ::: "memory");
}
template <int N>
__device__ __forceinline__ void cp_wait() {
    asm volatile("cp.async.wait_group %0;" :: "n"(N) : "memory");
}
__device__ __forceinline__ void ldsm_x4(uint32_t& r0, uint32_t& r1,
                                        uint32_t& r2, uint32_t& r3, uint32_t addr) {
    asm volatile("ldmatrix.sync.aligned.m8n8.x4.shared.b16 {%0,%1,%2,%3}, [%4];"
                 : "=r"(r0), "=r"(r1), "=r"(r2), "=r"(r3) : "r"(addr));
}
__device__ __forceinline__ void ldsm_x4_t(uint32_t& r0, uint32_t& r1,
                                          uint32_t& r2, uint32_t& r3, uint32_t addr) {
    asm volatile("ldmatrix.sync.aligned.m8n8.x4.trans.shared.b16 {%0,%1,%2,%3}, [%4];"
                 : "=r"(r0), "=r"(r1), "=r"(r2), "=r"(r3) : "r"(addr));
}
// fp16 inputs, fp32 accumulate
__device__ __forceinline__ void mma16816(float* d, const uint32_t* a, const uint32_t* b) {
    asm volatile(
        "mma.sync.aligned.m16n8k16.row.col.f32.f16.f16.f32 "
        "{%0,%1,%2,%3}, {%4,%5,%6,%7}, {%8,%9}, {%0,%1,%2,%3};"
        : "+f"(d[0]), "+f"(d[1]), "+f"(d[2]), "+f"(d[3])
        : "r"(a[0]), "r"(a[1]), "r"(a[2]), "r"(a[3]), "r"(b[0]), "r"(b[1]));
}
// Split two fp32 into packed fp16x2 hi + fp16x2 lo
__device__ __forceinline__ void split2(float v0, float v1, uint32_t& hi, uint32_t& lo) {
    __half h0 = __float2half_rn(v0), h1 = __float2half_rn(v1);
    __half l0 = __float2half_rn(v0 - __half2float(h0));
    __half l1 = __float2half_rn(v1 - __half2float(h1));
    __half2 Hv(h0, h1), Lv(l0, l1);
    hi = *(uint32_t*)&Hv; lo = *(uint32_t*)&Lv;
}

// ---------------------------------------------------------------------------
// fp32 -> fp16 hi/lo split, and fp32 -> fp16 single convert
// ---------------------------------------------------------------------------
__global__ __launch_bounds__(256)
void split_fp16(const float* __restrict__ in, __half* __restrict__ hi,
                __half* __restrict__ lo, int n4)
{
    int i = blockIdx.x * blockDim.x + threadIdx.x;
    if (i >= n4) return;
    float4 v = ((const float4*)in)[i];
    uint32_t h01, l01, h23, l23;
    split2(v.x, v.y, h01, l01);
    split2(v.z, v.w, h23, l23);
    ((uint32_t*)hi)[2 * i + 0] = h01; ((uint32_t*)hi)[2 * i + 1] = h23;
    ((uint32_t*)lo)[2 * i + 0] = l01; ((uint32_t*)lo)[2 * i + 1] = l23;
}

__global__ __launch_bounds__(256)
void conv_fp16(const float* __restrict__ in, __half* __restrict__ out, int n4)
{
    int i = blockIdx.x * blockDim.x + threadIdx.x;
    if (i >= n4) return;
    float4 v = ((const float4*)in)[i];
    __half2 a(__float2half_rn(v.x), __float2half_rn(v.y));
    __half2 b(__float2half_rn(v.z), __float2half_rn(v.w));
    ((uint32_t*)out)[2 * i + 0] = *(uint32_t*)&a;
    ((uint32_t*)out)[2 * i + 1] = *(uint32_t*)&b;
}

// ---------------------------------------------------------------------------
// HMMA GEMM (NT): C[m,n] = sum_k A[m,k]*B[n,k] + bias[n].
// A split fp16 (hi+lo), B single fp16: 2 MMA products (ah*b + al*b).
// 512 threads, 16 warps (4x4), warp tile 32x32, BK=32, 5-buffer ring.
// ---------------------------------------------------------------------------
constexpr int BK_   = 32;
constexpr int SKS_  = 40;
constexpr int MAT_E = 128 * SKS_;
constexpr int STAGE_E = 3 * MAT_E;               // Ah, Al, Bh
constexpr int NBUF_G = 5;
constexpr int GEMM_SMEM = NBUF_G * STAGE_E * 2;  // 153600 B

__device__ __forceinline__ void stage_loads(uint32_t sbuf,
    const __half* Ahi, const __half* Alo, const __half* Bh,
    int bm, int bn, int k0, int K, int tid)
{
    const __half* srcs[3] = { Ahi, Alo, Bh };
    const int r0s[3] = { bm, bm, bn };
    const int row = tid >> 2;
    const int cb  = (tid & 3) * 8;
    const uint32_t so = (row * SKS_ + cb) * 2;
#pragma unroll
    for (int m = 0; m < 3; m++) {
        const void* g = srcs[m] + (size_t)(r0s[m] + row) * K + k0 + cb;
        cp_async16(sbuf + m * MAT_E * 2 + so, g);
    }
    cp_commit();
}

template <int OUTMODE>
__global__ __launch_bounds__(512, 1)
void gemm_mma(const __half* __restrict__ Ahi, const __half* __restrict__ Alo,
              const __half* __restrict__ Bh2,
              const float* __restrict__ bias, float* __restrict__ Cf,
              __half* __restrict__ Chi, __half* __restrict__ Clo,
              int M, int N, int K)
{
    extern __shared__ __align__(128) __half smem[];
    const int tid  = threadIdx.x;
    const int wid  = tid >> 5;
    const int lane = tid & 31;
    const int wm   = wid >> 2;
    const int wn   = wid & 3;
    const int bm   = blockIdx.y * 128;
    const int bn   = blockIdx.x * 128;
    const uint32_t sbase = smem_u32(smem);

    float acc[2][4][4];
#pragma unroll
    for (int i = 0; i < 2; i++)
#pragma unroll
        for (int j = 0; j < 4; j++)
#pragma unroll
            for (int r = 0; r < 4; r++) acc[i][j][r] = 0.f;

    const int a_row = wm * 32 + (lane & 15);
    const int a_col = (lane >> 4) * 8;
    const int b_row = wn * 32 + ((lane >> 4) & 1) * 8 + (lane & 7);
    const int b_col = ((lane >> 3) & 1) * 8;

    const int S = K / BK_;   // 32

#pragma unroll
    for (int p = 0; p < 4; p++)
        stage_loads(sbase + p * STAGE_E * 2, Ahi, Alo, Bh2,
                    bm, bn, p * BK_, K, tid);

    int buf = 0, nbuf = 4 % NBUF_G;
    for (int s = 0; s < S; s++) {
        cp_wait<3>();
        __syncthreads();

        if (s + 4 < S)
            stage_loads(sbase + nbuf * STAGE_E * 2, Ahi, Alo, Bh2,
                        bm, bn, (s + 4) * BK_, K, tid);
        else
            cp_commit();

        const uint32_t sb  = sbase + buf * STAGE_E * 2;
        const uint32_t sAh = sb;
        const uint32_t sAl = sb + MAT_E * 2;
        const uint32_t sBh = sb + 2 * MAT_E * 2;

#pragma unroll
        for (int ks = 0; ks < 2; ks++) {
            uint32_t ah[2][4], al[2][4], bh[2][4];
            const int ac = a_col + ks * 16;
            const int bc = b_col + ks * 16;
#pragma unroll
            for (int mt = 0; mt < 2; mt++) {
                uint32_t ra = ((a_row + mt * 16) * SKS_ + ac) * 2;
                ldsm_x4(ah[mt][0], ah[mt][1], ah[mt][2], ah[mt][3], sAh + ra);
                ldsm_x4(al[mt][0], al[mt][1], al[mt][2], al[mt][3], sAl + ra);
            }
#pragma unroll
            for (int np = 0; np < 2; np++) {
                uint32_t rb = ((b_row + np * 16) * SKS_ + bc) * 2;
                ldsm_x4(bh[np][0], bh[np][1], bh[np][2], bh[np][3], sBh + rb);
            }
#pragma unroll
            for (int mt = 0; mt < 2; mt++)
#pragma unroll
                for (int nt = 0; nt < 4; nt++) {
                    const uint32_t* bp = &bh[nt >> 1][(nt & 1) * 2];
                    mma16816(acc[mt][nt], ah[mt], bp);
                    mma16816(acc[mt][nt], al[mt], bp);
                }
        }
        if (++buf == NBUF_G)  buf = 0;
        if (++nbuf == NBUF_G) nbuf = 0;
    }

    const int er = lane >> 2;
    const int ec = (lane & 3) * 2;
#pragma unroll
    for (int mt = 0; mt < 2; mt++) {
        const int row0 = bm + wm * 32 + mt * 16 + er;
#pragma unroll
        for (int nt = 0; nt < 4; nt++) {
            const int col = bn + wn * 32 + nt * 8 + ec;
            const float bx = bias[col], by = bias[col + 1];
            float v0 = acc[mt][nt][0] + bx, v1 = acc[mt][nt][1] + by;
            float v2 = acc[mt][nt][2] + bx, v3 = acc[mt][nt][3] + by;
            if (OUTMODE == 0) {
                *(float2*)(Cf + (size_t)row0 * N + col)       = make_float2(v0, v1);
                *(float2*)(Cf + (size_t)(row0 + 8) * N + col) = make_float2(v2, v3);
            } else {
                uint32_t uh, ul;
                split2(v0, v1, uh, ul);
                *(uint32_t*)(Chi + (size_t)row0 * N + col) = uh;
                *(uint32_t*)(Clo + (size_t)row0 * N + col) = ul;
                split2(v2, v3, uh, ul);
                *(uint32_t*)(Chi + (size_t)(row0 + 8) * N + col) = uh;
                *(uint32_t*)(Clo + (size_t)(row0 + 8) * N + col) = ul;
            }
        }
    }
}

// ---------------------------------------------------------------------------
// HMMA causal flash attention: Q split fp16, K/V single fp16 (from qkv_hi).
// 2-product QK and PV. CTA: 128 q-rows x (b,h). 8 warps x 16 rows.
// 64-key blocks, 3-buffer KV ring (Kh, Vh only).
// ---------------------------------------------------------------------------
constexpr int SKA_    = 72;
constexpr int QTILE_E = 128 * SKA_;
constexpr int KTILE_E = 64 * SKA_;
constexpr int ATT_STAGE_E = 2 * KTILE_E;          // Kh, Vh
constexpr int NBUF_A  = 3;
constexpr int ATT_SMEM = (2 * QTILE_E + NBUF_A * ATT_STAGE_E) * 2;  // 92160 B

__device__ __forceinline__ void stage_kv(uint32_t sbuf,
    const __half* qh, size_t bbase, int colK, int colV, int j0, int tid)
{
#pragma unroll
    for (int it = 0; it < 2; it++) {
        int s   = tid + it * 256;
        int row = s >> 3;
        int ch  = (s & 7) * 8;
        size_t g = bbase + (size_t)(j0 + row) * C3_;
        uint32_t so = (row * SKA_ + ch) * 2;
        cp_async16(sbuf + 0 * KTILE_E * 2 + so, qh + g + colK + ch);
        cp_async16(sbuf + 1 * KTILE_E * 2 + so, qh + g + colV + ch);
    }
}

__global__ __launch_bounds__(256, 1)
void attn_mma(const __half* __restrict__ qvh, const __half* __restrict__ qvl,
              __half* __restrict__ yh, __half* __restrict__ yl)
{
    extern __shared__ __align__(128) __half asm_[];
    const int tid  = threadIdx.x;
    const int wid  = tid >> 5;
    const int lane = tid & 31;
    const int qb = (int)gridDim.x - 1 - (int)blockIdx.x;
    const int bh = blockIdx.y;
    const int b  = bh >> 4;
    const int h  = bh & 15;
    const int q0 = qb * 128;
    const size_t bbase = (size_t)b * T_ * C3_;
    const int colQ = h * D_, colK = C_ + h * D_, colV = 2 * C_ + h * D_;

    const uint32_t sQh = smem_u32(asm_);
    const uint32_t sQl = sQh + QTILE_E * 2;
    const uint32_t sSt = sQl + QTILE_E * 2;

    const int nb = 2 * qb + 2;

    // Prologue: Q (hi+lo) + KV0 in group 0; KV1 in group 1.
#pragma unroll
    for (int it = 0; it < 4; it++) {
        int s   = tid + it * 256;
        int row = s >> 3;
        int ch  = (s & 7) * 8;
        size_t g = bbase + (size_t)(q0 + row) * C3_ + colQ + ch;
        uint32_t so = (row * SKA_ + ch) * 2;
        cp_async16(sQh + so, qvh + g);
        cp_async16(sQl + so, qvl + g);
    }
    stage_kv(sSt, qvh, bbase, colK, colV, 0, tid);
    cp_commit();
    if (1 < nb) stage_kv(sSt + ATT_STAGE_E * 2, qvh, bbase, colK, colV, 64, tid);
    cp_commit();

    uint32_t aqh[4][4], aql[4][4];
    float oc[8][4];
#pragma unroll
    for (int i = 0; i < 8; i++)
#pragma unroll
        for (int j = 0; j < 4; j++) oc[i][j] = 0.f;
    float mrow[2] = { -1e30f, -1e30f };
    float lrow[2] = { 0.f, 0.f };

    const float scl = 0.125f * 1.4426950408889634f;
    const int wrow0 = q0 + 16 * wid;

    int buf = 0, nbufi = 2;
    for (int j = 0; j < nb; j++) {
        cp_wait<1>();
        __syncthreads();

        if (j == 0) {
#pragma unroll
            for (int kc = 0; kc < 4; kc++) {
                uint32_t ra = (((16 * wid) + (lane & 15)) * SKA_
                               + (lane >> 4) * 8 + kc * 16) * 2;
                ldsm_x4(aqh[kc][0], aqh[kc][1], aqh[kc][2], aqh[kc][3], sQh + ra);
                ldsm_x4(aql[kc][0], aql[kc][1], aql[kc][2], aql[kc][3], sQl + ra);
            }
        }

        if (j + 2 < nb)
            stage_kv(sSt + nbufi * ATT_STAGE_E * 2, qvh,
                     bbase, colK, colV, (j + 2) * 64, tid);
        cp_commit();

        const int j0 = j * 64;
        if (j0 <= wrow0 + 15) {
            const uint32_t sb  = sSt + buf * ATT_STAGE_E * 2;
            const uint32_t sKh = sb;
            const uint32_t sVh = sb + KTILE_E * 2;

            float sc[8][4];
#pragma unroll
            for (int i = 0; i < 8; i++)
#pragma unroll
                for (int e = 0; e < 4; e++) sc[i][e] = 0.f;

            // ---- S = Q K^T (2-product: qh*k + ql*k) ----
            const int kb_r = ((lane >> 4) & 1) * 8 + (lane & 7);
            const int kb_c = ((lane >> 3) & 1) * 8;
#pragma unroll
            for (int kc = 0; kc < 4; kc++) {
                uint32_t kb[4][4];
#pragma unroll
                for (int g = 0; g < 4; g++) {
                    uint32_t off = ((g * 16 + kb_r) * SKA_ + kb_c + kc * 16) * 2;
                    ldsm_x4(kb[g][0], kb[g][1], kb[g][2], kb[g][3], sKh + off);
                }
#pragma unroll
                for (int nt = 0; nt < 8; nt++) {
                    const uint32_t* bp = &kb[nt >> 1][(nt & 1) * 2];
                    mma16816(sc[nt], aqh[kc], bp);
                    mma16816(sc[nt], aql[kc], bp);
                }
            }

            const bool anymask = (j0 + 63 > wrow0);
            const int r0g = wrow0 + (lane >> 2);
#pragma unroll
            for (int nt = 0; nt < 8; nt++)
#pragma unroll
                for (int e = 0; e < 4; e++) {
                    float v = sc[nt][e] * scl;
                    if (anymask) {
                        int key = j0 + nt * 8 + (lane & 3) * 2 + (e & 1);
                        int row = r0g + (e >> 1) * 8;
                        if (key > row) v = -1e30f;
                    }
                    sc[nt][e] = v;
                }

#pragma unroll
            for (int rr = 0; rr < 2; rr++) {
                float mx = -1e30f;
#pragma unroll
                for (int nt = 0; nt < 8; nt++)
                    mx = fmaxf(mx, fmaxf(sc[nt][2 * rr], sc[nt][2 * rr + 1]));
                mx = fmaxf(mx, __shfl_xor_sync(0xffffffffu, mx, 1));
                mx = fmaxf(mx, __shfl_xor_sync(0xffffffffu, mx, 2));
                float mnew = fmaxf(mrow[rr], mx);
                float al   = exp2f(mrow[rr] - mnew);
                mrow[rr] = mnew;
                float rs = 0.f;
#pragma unroll
                for (int nt = 0; nt < 8; nt++) {
                    float p0 = exp2f(sc[nt][2 * rr]     - mnew);
                    float p1 = exp2f(sc[nt][2 * rr + 1] - mnew);
                    sc[nt][2 * rr] = p0; sc[nt][2 * rr + 1] = p1;
                    rs += p0 + p1;
                }
                rs += __shfl_xor_sync(0xffffffffu, rs, 1);
                rs += __shfl_xor_sync(0xffffffffu, rs, 2);
                lrow[rr] = lrow[rr] * al + rs;
#pragma unroll
                for (int nd = 0; nd < 8; nd++) {
                    oc[nd][2 * rr]     *= al;
                    oc[nd][2 * rr + 1] *= al;
                }
            }

            // ---- O += P V (2-product: ph*v + pl*v) ----
#pragma unroll
            for (int t = 0; t < 4; t++) {
                uint32_t ph[4], pl[4];
                split2(sc[2 * t][0],     sc[2 * t][1],     ph[0], pl[0]);
                split2(sc[2 * t][2],     sc[2 * t][3],     ph[1], pl[1]);
                split2(sc[2 * t + 1][0], sc[2 * t + 1][1], ph[2], pl[2]);
                split2(sc[2 * t + 1][2], sc[2 * t + 1][3], ph[3], pl[3]);
                const int vkey = 16 * t + ((lane >> 3) & 1) * 8 + (lane & 7);
                const int vcb  = (lane >> 4) * 8;
#pragma unroll
                for (int nd2 = 0; nd2 < 4; nd2++) {
                    uint32_t vf[4];
                    uint32_t off = (vkey * SKA_ + nd2 * 16 + vcb) * 2;
                    ldsm_x4_t(vf[0], vf[1], vf[2], vf[3], sVh + off);
                    mma16816(oc[2 * nd2],     ph, &vf[0]);
                    mma16816(oc[2 * nd2],     pl, &vf[0]);
                    mma16816(oc[2 * nd2 + 1], ph, &vf[2]);
                    mma16816(oc[2 * nd2 + 1], pl, &vf[2]);
                }
            }
        }
        if (++buf == NBUF_A)   buf = 0;
        if (++nbufi == NBUF_A) nbufi = 0;
    }

    const float inv0 = 1.0f / lrow[0];
    const float inv1 = 1.0f / lrow[1];
    const int gr0 = wrow0 + (lane >> 2);
    const int gr1 = gr0 + 8;
    const int colb = h * D_ + (lane & 3) * 2;
#pragma unroll
    for (int nd = 0; nd < 8; nd++) {
        const int col = colb + nd * 8;
        uint32_t uh, ul;
        split2(oc[nd][0] * inv0, oc[nd][1] * inv0, uh, ul);
        *(uint32_t*)(yh + ((size_t)b * T_ + gr0) * C_ + col) = uh;
        *(uint32_t*)(yl + ((size_t)b * T_ + gr0) * C_ + col) = ul;
        split2(oc[nd][2] * inv1, oc[nd][3] * inv1, uh, ul);
        *(uint32_t*)(yh + ((size_t)b * T_ + gr1) * C_ + col) = uh;
        *(uint32_t*)(yl + ((size_t)b * T_ + gr1) * C_ + col) = ul;
    }
}

// ---------------------------------------------------------------------------
extern "C" void kernel_launch(void* const* d_in, const int* in_sizes, int n_in,
                              void* d_out, int out_size)
{
    const float* x      = (const float*)d_in[0];
    const float* w_attn = (const float*)d_in[1];
    const float* b_attn = (const float*)d_in[2];
    const float* w_proj = (const float*)d_in[3];
    const float* b_proj = (const float*)d_in[4];
    float* out = (float*)d_out;

    __half *xh, *xl, *wa, *wp, *qh, *ql, *yh, *yl;
    cudaGetSymbolAddress((void**)&xh, g_x_hi);
    cudaGetSymbolAddress((void**)&xl, g_x_lo);
    cudaGetSymbolAddress((void**)&wa, g_wa);
    cudaGetSymbolAddress((void**)&wp, g_wp);
    cudaGetSymbolAddress((void**)&qh, g_qkv_hi);
    cudaGetSymbolAddress((void**)&ql, g_qkv_lo);
    cudaGetSymbolAddress((void**)&yh, g_y_hi);
    cudaGetSymbolAddress((void**)&yl, g_y_lo);

    cudaFuncSetAttribute(gemm_mma<0>, cudaFuncAttributeMaxDynamicSharedMemorySize, GEMM_SMEM);
    cudaFuncSetAttribute(gemm_mma<1>, cudaFuncAttributeMaxDynamicSharedMemorySize, GEMM_SMEM);
    cudaFuncSetAttribute(attn_mma,    cudaFuncAttributeMaxDynamicSharedMemorySize, ATT_SMEM);

    // Prepare fp16 operands
    {
        int n4;
        n4 = M_ * C_ / 4;   split_fp16<<<(n4 + 255) / 256, 256>>>(x, xh, xl, n4);
        n4 = C3_ * C_ / 4;  conv_fp16 <<<(n4 + 255) / 256, 256>>>(w_attn, wa, n4);
        n4 = C_ * C_ / 4;   conv_fp16 <<<(n4 + 255) / 256, 256>>>(w_proj, wp, n4);
    }

    // 1) QKV projection -> fp16 hi/lo qkv (2-product)
    {
        dim3 grid(C3_ / 128, M_ / 128);
        gemm_mma<1><<<grid, 512, GEMM_SMEM>>>(xh, xl, wa, b_attn,
                                              nullptr, qh, ql, M_, C3_, C_);
    }

    // 2) HMMA causal flash attention -> fp16 hi/lo y (2-product QK and PV)
    {
        dim3 grid(T_ / 128, B_ * H_);
        attn_mma<<<grid, 256, ATT_SMEM>>>(qh, ql, yh, yl);
    }

    // 3) Output projection -> fp32 out (2-product)
    {
        dim3 grid(C_ / 128, M_ / 128);
        gemm_mma<0><<<grid, 512, GEMM_SMEM>>>(yh, yl, wp, b_proj,
                                              out, nullptr, nullptr, M_, C_, C_);
    }
}

// round 9
// speedup vs baseline: 2.2429x; 1.5314x over previous
#include <cuda_runtime.h>
#include <cuda_fp16.h>
#include <cstdint>

// Problem constants
constexpr int B_  = 2;
constexpr int T_  = 2048;
constexpr int C_  = 1024;
constexpr int H_  = 16;
constexpr int D_  = 64;
constexpr int C3_ = 3 * C_;   // 3072
constexpr int M_  = B_ * T_;  // 4096

// Scratch (allocation-free rule: __device__ globals). Single fp16 everywhere.
__device__ __half g_x  [(size_t)M_  * C_];
__device__ __half g_wa [(size_t)C3_ * C_];
__device__ __half g_wp [(size_t)C_  * C_];
__device__ __half g_qkv[(size_t)M_  * C3_];
__device__ __half g_y  [(size_t)M_  * C_];

// ---------------------------------------------------------------------------
// Baseline-PTX helpers (sm_80+ only)
// ---------------------------------------------------------------------------
__device__ __forceinline__ uint32_t smem_u32(const void* p) {
    uint32_t a;
    asm("{ .reg .u64 t; cvta.to.shared.u64 t, %1; cvt.u32.u64 %0, t; }"
        : "=r"(a) : "l"(p));
    return a;
}
__device__ __forceinline__ void cp_async16(uint32_t saddr, const void* gaddr) {
    asm volatile("cp.async.cg.shared.global [%0], [%1], 16;"
                 :: "r"(saddr), "l"(gaddr) : "memory");
}
__device__ __forceinline__ void cp_commit() {
    asm volatile("cp.async.commit_group;" ::: "memory");
}
template <int N>
__device__ __forceinline__ void cp_wait() {
    asm volatile("cp.async.wait_group %0;" :: "n"(N) : "memory");
}
__device__ __forceinline__ void ldsm_x4(uint32_t& r0, uint32_t& r1,
                                        uint32_t& r2, uint32_t& r3, uint32_t addr) {
    asm volatile("ldmatrix.sync.aligned.m8n8.x4.shared.b16 {%0,%1,%2,%3}, [%4];"
                 : "=r"(r0), "=r"(r1), "=r"(r2), "=r"(r3) : "r"(addr));
}
__device__ __forceinline__ void ldsm_x4_t(uint32_t& r0, uint32_t& r1,
                                          uint32_t& r2, uint32_t& r3, uint32_t addr) {
    asm volatile("ldmatrix.sync.aligned.m8n8.x4.trans.shared.b16 {%0,%1,%2,%3}, [%4];"
                 : "=r"(r0), "=r"(r1), "=r"(r2), "=r"(r3) : "r"(addr));
}
// fp16 inputs, fp32 accumulate
__device__ __forceinline__ void mma16816(float* d, const uint32_t* a, const uint32_t* b) {
    asm volatile(
        "mma.sync.aligned.m16n8k16.row.col.f32.f16.f16.f32 "
        "{%0,%1,%2,%3}, {%4,%5,%6,%7}, {%8,%9}, {%0,%1,%2,%3};"
        : "+f"(d[0]), "+f"(d[1]), "+f"(d[2]), "+f"(d[3])
        : "r"(a[0]), "r"(a[1]), "r"(a[2]), "r"(a[3]), "r"(b[0]), "r"(b[1]));
}
// Pack two fp32 into fp16x2
__device__ __forceinline__ void pack2(float v0, float v1, uint32_t& u) {
    __half2 H(__float2half_rn(v0), __float2half_rn(v1));
    u = *(uint32_t*)&H;
}

// ---------------------------------------------------------------------------
// fp32 -> fp16 convert
// ---------------------------------------------------------------------------
__global__ __launch_bounds__(256)
void conv_fp16(const float* __restrict__ in, __half* __restrict__ out, int n4)
{
    int i = blockIdx.x * blockDim.x + threadIdx.x;
    if (i >= n4) return;
    float4 v = ((const float4*)in)[i];
    uint32_t a, b;
    pack2(v.x, v.y, a);
    pack2(v.z, v.w, b);
    ((uint32_t*)out)[2 * i + 0] = a;
    ((uint32_t*)out)[2 * i + 1] = b;
}

// ---------------------------------------------------------------------------
// HMMA GEMM (NT): C[m,n] = sum_k A[m,k]*B[n,k] + bias[n], single fp16.
// 512 threads, 16 warps (4x4), warp tile 32x32, BK=32, 5-buffer ring.
// ---------------------------------------------------------------------------
constexpr int BK_   = 32;
constexpr int SKS_  = 40;
constexpr int MAT_E = 128 * SKS_;
constexpr int STAGE_E = 2 * MAT_E;               // A, B
constexpr int NBUF_G = 5;
constexpr int GEMM_SMEM = NBUF_G * STAGE_E * 2;  // 102400 B

__device__ __forceinline__ void stage_loads(uint32_t sbuf,
    const __half* A, const __half* Bm,
    int bm, int bn, int k0, int K, int tid)
{
    const int row = tid >> 2;
    const int cb  = (tid & 3) * 8;
    const uint32_t so = (row * SKS_ + cb) * 2;
    cp_async16(sbuf + so,              A  + (size_t)(bm + row) * K + k0 + cb);
    cp_async16(sbuf + MAT_E * 2 + so,  Bm + (size_t)(bn + row) * K + k0 + cb);
    cp_commit();
}

template <int OUTMODE>
__global__ __launch_bounds__(512, 1)
void gemm_mma(const __half* __restrict__ A, const __half* __restrict__ Bm,
              const float* __restrict__ bias, float* __restrict__ Cf,
              __half* __restrict__ Ch, int M, int N, int K)
{
    extern __shared__ __align__(128) __half smem[];
    const int tid  = threadIdx.x;
    const int wid  = tid >> 5;
    const int lane = tid & 31;
    const int wm   = wid >> 2;
    const int wn   = wid & 3;
    const int bm   = blockIdx.y * 128;
    const int bn   = blockIdx.x * 128;
    const uint32_t sbase = smem_u32(smem);

    float acc[2][4][4];
#pragma unroll
    for (int i = 0; i < 2; i++)
#pragma unroll
        for (int j = 0; j < 4; j++)
#pragma unroll
            for (int r = 0; r < 4; r++) acc[i][j][r] = 0.f;

    const int a_row = wm * 32 + (lane & 15);
    const int a_col = (lane >> 4) * 8;
    const int b_row = wn * 32 + ((lane >> 4) & 1) * 8 + (lane & 7);
    const int b_col = ((lane >> 3) & 1) * 8;

    const int S = K / BK_;   // 32

#pragma unroll
    for (int p = 0; p < 4; p++)
        stage_loads(sbase + p * STAGE_E * 2, A, Bm, bm, bn, p * BK_, K, tid);

    int buf = 0, nbuf = 4 % NBUF_G;
    for (int s = 0; s < S; s++) {
        cp_wait<3>();
        __syncthreads();

        if (s + 4 < S)
            stage_loads(sbase + nbuf * STAGE_E * 2, A, Bm,
                        bm, bn, (s + 4) * BK_, K, tid);
        else
            cp_commit();

        const uint32_t sA = sbase + buf * STAGE_E * 2;
        const uint32_t sB = sA + MAT_E * 2;

#pragma unroll
        for (int ks = 0; ks < 2; ks++) {
            uint32_t af[2][4], bf[2][4];
            const int ac = a_col + ks * 16;
            const int bc = b_col + ks * 16;
#pragma unroll
            for (int mt = 0; mt < 2; mt++) {
                uint32_t ra = ((a_row + mt * 16) * SKS_ + ac) * 2;
                ldsm_x4(af[mt][0], af[mt][1], af[mt][2], af[mt][3], sA + ra);
            }
#pragma unroll
            for (int np = 0; np < 2; np++) {
                uint32_t rb = ((b_row + np * 16) * SKS_ + bc) * 2;
                ldsm_x4(bf[np][0], bf[np][1], bf[np][2], bf[np][3], sB + rb);
            }
#pragma unroll
            for (int mt = 0; mt < 2; mt++)
#pragma unroll
                for (int nt = 0; nt < 4; nt++)
                    mma16816(acc[mt][nt], af[mt], &bf[nt >> 1][(nt & 1) * 2]);
        }
        if (++buf == NBUF_G)  buf = 0;
        if (++nbuf == NBUF_G) nbuf = 0;
    }

    const int er = lane >> 2;
    const int ec = (lane & 3) * 2;
#pragma unroll
    for (int mt = 0; mt < 2; mt++) {
        const int row0 = bm + wm * 32 + mt * 16 + er;
#pragma unroll
        for (int nt = 0; nt < 4; nt++) {
            const int col = bn + wn * 32 + nt * 8 + ec;
            const float bx = bias[col], by = bias[col + 1];
            float v0 = acc[mt][nt][0] + bx, v1 = acc[mt][nt][1] + by;
            float v2 = acc[mt][nt][2] + bx, v3 = acc[mt][nt][3] + by;
            if (OUTMODE == 0) {
                *(float2*)(Cf + (size_t)row0 * N + col)       = make_float2(v0, v1);
                *(float2*)(Cf + (size_t)(row0 + 8) * N + col) = make_float2(v2, v3);
            } else {
                uint32_t u;
                pack2(v0, v1, u);
                *(uint32_t*)(Ch + (size_t)row0 * N + col) = u;
                pack2(v2, v3, u);
                *(uint32_t*)(Ch + (size_t)(row0 + 8) * N + col) = u;
            }
        }
    }
}

// ---------------------------------------------------------------------------
// HMMA causal flash attention, single fp16 (Q, K, V, P all single).
// CTA: 128 q-rows x (b,h). 8 warps x 16 rows. 64-key blocks, 3-buffer KV ring.
// ---------------------------------------------------------------------------
constexpr int SKA_    = 72;
constexpr int QTILE_E = 128 * SKA_;
constexpr int KTILE_E = 64 * SKA_;
constexpr int ATT_STAGE_E = 2 * KTILE_E;          // K, V
constexpr int NBUF_A  = 3;
constexpr int ATT_SMEM = (QTILE_E + NBUF_A * ATT_STAGE_E) * 2;  // 73728 B

__device__ __forceinline__ void stage_kv(uint32_t sbuf,
    const __half* qv, size_t bbase, int colK, int colV, int j0, int tid)
{
#pragma unroll
    for (int it = 0; it < 2; it++) {
        int s   = tid + it * 256;
        int row = s >> 3;
        int ch  = (s & 7) * 8;
        size_t g = bbase + (size_t)(j0 + row) * C3_;
        uint32_t so = (row * SKA_ + ch) * 2;
        cp_async16(sbuf + 0 * KTILE_E * 2 + so, qv + g + colK + ch);
        cp_async16(sbuf + 1 * KTILE_E * 2 + so, qv + g + colV + ch);
    }
}

__global__ __launch_bounds__(256)
void attn_mma(const __half* __restrict__ qv, __half* __restrict__ y)
{
    extern __shared__ __align__(128) __half asm_[];
    const int tid  = threadIdx.x;
    const int wid  = tid >> 5;
    const int lane = tid & 31;
    const int qb = (int)gridDim.x - 1 - (int)blockIdx.x;
    const int bh = blockIdx.y;
    const int b  = bh >> 4;
    const int h  = bh & 15;
    const int q0 = qb * 128;
    const size_t bbase = (size_t)b * T_ * C3_;
    const int colQ = h * D_, colK = C_ + h * D_, colV = 2 * C_ + h * D_;

    const uint32_t sQ  = smem_u32(asm_);
    const uint32_t sSt = sQ + QTILE_E * 2;

    const int nb = 2 * qb + 2;

    // Prologue: Q + KV0 in group 0; KV1 in group 1.
#pragma unroll
    for (int it = 0; it < 4; it++) {
        int s   = tid + it * 256;
        int row = s >> 3;
        int ch  = (s & 7) * 8;
        size_t g = bbase + (size_t)(q0 + row) * C3_ + colQ + ch;
        cp_async16(sQ + (row * SKA_ + ch) * 2, qv + g);
    }
    stage_kv(sSt, qv, bbase, colK, colV, 0, tid);
    cp_commit();
    if (1 < nb) stage_kv(sSt + ATT_STAGE_E * 2, qv, bbase, colK, colV, 64, tid);
    cp_commit();

    uint32_t aq[4][4];
    float oc[8][4];
#pragma unroll
    for (int i = 0; i < 8; i++)
#pragma unroll
        for (int j = 0; j < 4; j++) oc[i][j] = 0.f;
    float mrow[2] = { -1e30f, -1e30f };
    float lrow[2] = { 0.f, 0.f };

    const float scl = 0.125f * 1.4426950408889634f;
    const int wrow0 = q0 + 16 * wid;

    int buf = 0, nbufi = 2;
    for (int j = 0; j < nb; j++) {
        cp_wait<1>();
        __syncthreads();

        if (j == 0) {
#pragma unroll
            for (int kc = 0; kc < 4; kc++) {
                uint32_t ra = (((16 * wid) + (lane & 15)) * SKA_
                               + (lane >> 4) * 8 + kc * 16) * 2;
                ldsm_x4(aq[kc][0], aq[kc][1], aq[kc][2], aq[kc][3], sQ + ra);
            }
        }

        if (j + 2 < nb)
            stage_kv(sSt + nbufi * ATT_STAGE_E * 2, qv,
                     bbase, colK, colV, (j + 2) * 64, tid);
        cp_commit();

        const int j0 = j * 64;
        if (j0 <= wrow0 + 15) {
            const uint32_t sK = sSt + buf * ATT_STAGE_E * 2;
            const uint32_t sV = sK + KTILE_E * 2;

            float sc[8][4];
#pragma unroll
            for (int i = 0; i < 8; i++)
#pragma unroll
                for (int e = 0; e < 4; e++) sc[i][e] = 0.f;

            // ---- S = Q K^T (single product) ----
            const int kb_r = ((lane >> 4) & 1) * 8 + (lane & 7);
            const int kb_c = ((lane >> 3) & 1) * 8;
#pragma unroll
            for (int kc = 0; kc < 4; kc++) {
                uint32_t kb[4][4];
#pragma unroll
                for (int g = 0; g < 4; g++) {
                    uint32_t off = ((g * 16 + kb_r) * SKA_ + kb_c + kc * 16) * 2;
                    ldsm_x4(kb[g][0], kb[g][1], kb[g][2], kb[g][3], sK + off);
                }
#pragma unroll
                for (int nt = 0; nt < 8; nt++)
                    mma16816(sc[nt], aq[kc], &kb[nt >> 1][(nt & 1) * 2]);
            }

            const bool anymask = (j0 + 63 > wrow0);
            const int r0g = wrow0 + (lane >> 2);
#pragma unroll
            for (int nt = 0; nt < 8; nt++)
#pragma unroll
                for (int e = 0; e < 4; e++) {
                    float v = sc[nt][e] * scl;
                    if (anymask) {
                        int key = j0 + nt * 8 + (lane & 3) * 2 + (e & 1);
                        int row = r0g + (e >> 1) * 8;
                        if (key > row) v = -1e30f;
                    }
                    sc[nt][e] = v;
                }

#pragma unroll
            for (int rr = 0; rr < 2; rr++) {
                float mx = -1e30f;
#pragma unroll
                for (int nt = 0; nt < 8; nt++)
                    mx = fmaxf(mx, fmaxf(sc[nt][2 * rr], sc[nt][2 * rr + 1]));
                mx = fmaxf(mx, __shfl_xor_sync(0xffffffffu, mx, 1));
                mx = fmaxf(mx, __shfl_xor_sync(0xffffffffu, mx, 2));
                float mnew = fmaxf(mrow[rr], mx);
                float al   = exp2f(mrow[rr] - mnew);
                mrow[rr] = mnew;
                float rs = 0.f;
#pragma unroll
                for (int nt = 0; nt < 8; nt++) {
                    float p0 = exp2f(sc[nt][2 * rr]     - mnew);
                    float p1 = exp2f(sc[nt][2 * rr + 1] - mnew);
                    sc[nt][2 * rr] = p0; sc[nt][2 * rr + 1] = p1;
                    rs += p0 + p1;
                }
                rs += __shfl_xor_sync(0xffffffffu, rs, 1);
                rs += __shfl_xor_sync(0xffffffffu, rs, 2);
                lrow[rr] = lrow[rr] * al + rs;
#pragma unroll
                for (int nd = 0; nd < 8; nd++) {
                    oc[nd][2 * rr]     *= al;
                    oc[nd][2 * rr + 1] *= al;
                }
            }

            // ---- O += P V (single product) ----
#pragma unroll
            for (int t = 0; t < 4; t++) {
                uint32_t ph[4];
                pack2(sc[2 * t][0],     sc[2 * t][1],     ph[0]);
                pack2(sc[2 * t][2],     sc[2 * t][3],     ph[1]);
                pack2(sc[2 * t + 1][0], sc[2 * t + 1][1], ph[2]);
                pack2(sc[2 * t + 1][2], sc[2 * t + 1][3], ph[3]);
                const int vkey = 16 * t + ((lane >> 3) & 1) * 8 + (lane & 7);
                const int vcb  = (lane >> 4) * 8;
#pragma unroll
                for (int nd2 = 0; nd2 < 4; nd2++) {
                    uint32_t vf[4];
                    uint32_t off = (vkey * SKA_ + nd2 * 16 + vcb) * 2;
                    ldsm_x4_t(vf[0], vf[1], vf[2], vf[3], sV + off);
                    mma16816(oc[2 * nd2],     ph, &vf[0]);
                    mma16816(oc[2 * nd2 + 1], ph, &vf[2]);
                }
            }
        }
        if (++buf == NBUF_A)   buf = 0;
        if (++nbufi == NBUF_A) nbufi = 0;
    }

    // ---- epilogue: normalize, fp16 store ----
    const float inv0 = 1.0f / lrow[0];
    const float inv1 = 1.0f / lrow[1];
    const int gr0 = wrow0 + (lane >> 2);
    const int gr1 = gr0 + 8;
    const int colb = h * D_ + (lane & 3) * 2;
#pragma unroll
    for (int nd = 0; nd < 8; nd++) {
        const int col = colb + nd * 8;
        uint32_t u;
        pack2(oc[nd][0] * inv0, oc[nd][1] * inv0, u);
        *(uint32_t*)(y + ((size_t)b * T_ + gr0) * C_ + col) = u;
        pack2(oc[nd][2] * inv1, oc[nd][3] * inv1, u);
        *(uint32_t*)(y + ((size_t)b * T_ + gr1) * C_ + col) = u;
    }
}

// ---------------------------------------------------------------------------
extern "C" void kernel_launch(void* const* d_in, const int* in_sizes, int n_in,
                              void* d_out, int out_size)
{
    const float* x      = (const float*)d_in[0];
    const float* w_attn = (const float*)d_in[1];
    const float* b_attn = (const float*)d_in[2];
    const float* w_proj = (const float*)d_in[3];
    const float* b_proj = (const float*)d_in[4];
    float* out = (float*)d_out;

    __half *xc, *wa, *wp, *qk, *yb;
    cudaGetSymbolAddress((void**)&xc, g_x);
    cudaGetSymbolAddress((void**)&wa, g_wa);
    cudaGetSymbolAddress((void**)&wp, g_wp);
    cudaGetSymbolAddress((void**)&qk, g_qkv);
    cudaGetSymbolAddress((void**)&yb, g_y);

    cudaFuncSetAttribute(gemm_mma<0>, cudaFuncAttributeMaxDynamicSharedMemorySize, GEMM_SMEM);
    cudaFuncSetAttribute(gemm_mma<1>, cudaFuncAttributeMaxDynamicSharedMemorySize, GEMM_SMEM);
    cudaFuncSetAttribute(attn_mma,    cudaFuncAttributeMaxDynamicSharedMemorySize, ATT_SMEM);

    // Convert operands to fp16
    {
        int n4;
        n4 = M_ * C_ / 4;   conv_fp16<<<(n4 + 255) / 256, 256>>>(x,      xc, n4);
        n4 = C3_ * C_ / 4;  conv_fp16<<<(n4 + 255) / 256, 256>>>(w_attn, wa, n4);
        n4 = C_ * C_ / 4;   conv_fp16<<<(n4 + 255) / 256, 256>>>(w_proj, wp, n4);
    }

    // 1) QKV projection -> fp16 qkv
    {
        dim3 grid(C3_ / 128, M_ / 128);
        gemm_mma<1><<<grid, 512, GEMM_SMEM>>>(xc, wa, b_attn, nullptr, qk,
                                              M_, C3_, C_);
    }

    // 2) HMMA causal flash attention -> fp16 y
    {
        dim3 grid(T_ / 128, B_ * H_);
        attn_mma<<<grid, 256, ATT_SMEM>>>(qk, yb);
    }

    // 3) Output projection -> fp32 out
    {
        dim3 grid(C_ / 128, M_ / 128);
        gemm_mma<0><<<grid, 512, GEMM_SMEM>>>(yb, wp, b_proj, out, nullptr,
                                              M_, C_, C_);
    }
}

// round 10
// speedup vs baseline: 2.3069x; 1.0285x over previous
#include <cuda_runtime.h>
#include <cuda_fp16.h>
#include <cstdint>

// Problem constants
constexpr int B_  = 2;
constexpr int T_  = 2048;
constexpr int C_  = 1024;
constexpr int H_  = 16;
constexpr int D_  = 64;
constexpr int C3_ = 3 * C_;   // 3072
constexpr int M_  = B_ * T_;  // 4096

// Scratch (allocation-free rule: __device__ globals). Single fp16 everywhere.
__device__ __half g_x  [(size_t)M_  * C_];
__device__ __half g_wa [(size_t)C3_ * C_];
__device__ __half g_wp [(size_t)C_  * C_];
__device__ __half g_qkv[(size_t)M_  * C3_];
__device__ __half g_y  [(size_t)M_  * C_];

// ---------------------------------------------------------------------------
// Baseline-PTX helpers (sm_80+ only)
// ---------------------------------------------------------------------------
__device__ __forceinline__ uint32_t smem_u32(const void* p) {
    uint32_t a;
    asm("{ .reg .u64 t; cvta.to.shared.u64 t, %1; cvt.u32.u64 %0, t; }"
        : "=r"(a) : "l"(p));
    return a;
}
__device__ __forceinline__ void cp_async16(uint32_t saddr, const void* gaddr) {
    asm volatile("cp.async.cg.shared.global [%0], [%1], 16;"
                 :: "r"(saddr), "l"(gaddr) : "memory");
}
__device__ __forceinline__ void cp_commit() {
    asm volatile("cp.async.commit_group;" ::: "memory");
}
template <int N>
__device__ __forceinline__ void cp_wait() {
    asm volatile("cp.async.wait_group %0;" :: "n"(N) : "memory");
}
__device__ __forceinline__ void ldsm_x4(uint32_t& r0, uint32_t& r1,
                                        uint32_t& r2, uint32_t& r3, uint32_t addr) {
    asm volatile("ldmatrix.sync.aligned.m8n8.x4.shared.b16 {%0,%1,%2,%3}, [%4];"
                 : "=r"(r0), "=r"(r1), "=r"(r2), "=r"(r3) : "r"(addr));
}
__device__ __forceinline__ void ldsm_x4_t(uint32_t& r0, uint32_t& r1,
                                          uint32_t& r2, uint32_t& r3, uint32_t addr) {
    asm volatile("ldmatrix.sync.aligned.m8n8.x4.trans.shared.b16 {%0,%1,%2,%3}, [%4];"
                 : "=r"(r0), "=r"(r1), "=r"(r2), "=r"(r3) : "r"(addr));
}
// fp16 inputs, fp32 accumulate
__device__ __forceinline__ void mma16816(float* d, const uint32_t* a, const uint32_t* b) {
    asm volatile(
        "mma.sync.aligned.m16n8k16.row.col.f32.f16.f16.f32 "
        "{%0,%1,%2,%3}, {%4,%5,%6,%7}, {%8,%9}, {%0,%1,%2,%3};"
        : "+f"(d[0]), "+f"(d[1]), "+f"(d[2]), "+f"(d[3])
        : "r"(a[0]), "r"(a[1]), "r"(a[2]), "r"(a[3]), "r"(b[0]), "r"(b[1]));
}
__device__ __forceinline__ void pack2(float v0, float v1, uint32_t& u) {
    __half2 H(__float2half_rn(v0), __float2half_rn(v1));
    u = *(uint32_t*)&H;
}

// ---------------------------------------------------------------------------
// fp32 -> fp16 convert
// ---------------------------------------------------------------------------
__global__ __launch_bounds__(256)
void conv_fp16(const float* __restrict__ in, __half* __restrict__ out, int n4)
{
    int i = blockIdx.x * blockDim.x + threadIdx.x;
    if (i >= n4) return;
    float4 v = ((const float4*)in)[i];
    uint32_t a, b;
    pack2(v.x, v.y, a);
    pack2(v.z, v.w, b);
    ((uint32_t*)out)[2 * i + 0] = a;
    ((uint32_t*)out)[2 * i + 1] = b;
}

// ---------------------------------------------------------------------------
// HMMA GEMM (NT): C[m,n] = sum_k A[m,k]*B[n,k] + bias[n], single fp16.
// 512 threads, 16 warps (4x4), warp tile 32x32, BK=64, 4-buffer ring (depth 3).
// ---------------------------------------------------------------------------
constexpr int BK_   = 64;
constexpr int SKS_  = 72;                        // halfs per row (144 B, conflict-free)
constexpr int MAT_E = 128 * SKS_;                // 9216 halfs
constexpr int STAGE_E = 2 * MAT_E;               // A, B
constexpr int NBUF_G = 4;
constexpr int GEMM_SMEM = NBUF_G * STAGE_E * 2;  // 147456 B

__device__ __forceinline__ void stage_loads(uint32_t sbuf,
    const __half* A, const __half* Bm,
    int bm, int bn, int k0, int K, int tid)
{
#pragma unroll
    for (int it = 0; it < 2; it++) {
        int s   = tid + it * 512;          // 0..1023
        int row = s >> 3;                  // 0..127
        int cb  = (s & 7) * 8;             // 0..56
        uint32_t so = (row * SKS_ + cb) * 2;
        cp_async16(sbuf + so,             A  + (size_t)(bm + row) * K + k0 + cb);
        cp_async16(sbuf + MAT_E * 2 + so, Bm + (size_t)(bn + row) * K + k0 + cb);
    }
    cp_commit();
}

template <int OUTMODE>
__global__ __launch_bounds__(512, 1)
void gemm_mma(const __half* __restrict__ A, const __half* __restrict__ Bm,
              const float* __restrict__ bias, float* __restrict__ Cf,
              __half* __restrict__ Ch, int M, int N, int K)
{
    extern __shared__ __align__(128) __half smem[];
    const int tid  = threadIdx.x;
    const int wid  = tid >> 5;
    const int lane = tid & 31;
    const int wm   = wid >> 2;
    const int wn   = wid & 3;
    const int bm   = blockIdx.y * 128;
    const int bn   = blockIdx.x * 128;
    const uint32_t sbase = smem_u32(smem);

    float acc[2][4][4];
#pragma unroll
    for (int i = 0; i < 2; i++)
#pragma unroll
        for (int j = 0; j < 4; j++)
#pragma unroll
            for (int r = 0; r < 4; r++) acc[i][j][r] = 0.f;

    const int a_row = wm * 32 + (lane & 15);
    const int a_col = (lane >> 4) * 8;
    const int b_row = wn * 32 + ((lane >> 4) & 1) * 8 + (lane & 7);
    const int b_col = ((lane >> 3) & 1) * 8;

    const int S = K / BK_;   // 16

#pragma unroll
    for (int p = 0; p < 3; p++)
        stage_loads(sbase + p * STAGE_E * 2, A, Bm, bm, bn, p * BK_, K, tid);

    int buf = 0, nbuf = 3;
    for (int s = 0; s < S; s++) {
        cp_wait<2>();
        __syncthreads();

        if (s + 3 < S)
            stage_loads(sbase + nbuf * STAGE_E * 2, A, Bm,
                        bm, bn, (s + 3) * BK_, K, tid);
        else
            cp_commit();

        const uint32_t sA = sbase + buf * STAGE_E * 2;
        const uint32_t sB = sA + MAT_E * 2;

#pragma unroll
        for (int ks = 0; ks < 4; ks++) {
            uint32_t af[2][4], bf[2][4];
            const int ac = a_col + ks * 16;
            const int bc = b_col + ks * 16;
#pragma unroll
            for (int mt = 0; mt < 2; mt++) {
                uint32_t ra = ((a_row + mt * 16) * SKS_ + ac) * 2;
                ldsm_x4(af[mt][0], af[mt][1], af[mt][2], af[mt][3], sA + ra);
            }
#pragma unroll
            for (int np = 0; np < 2; np++) {
                uint32_t rb = ((b_row + np * 16) * SKS_ + bc) * 2;
                ldsm_x4(bf[np][0], bf[np][1], bf[np][2], bf[np][3], sB + rb);
            }
#pragma unroll
            for (int mt = 0; mt < 2; mt++)
#pragma unroll
                for (int nt = 0; nt < 4; nt++)
                    mma16816(acc[mt][nt], af[mt], &bf[nt >> 1][(nt & 1) * 2]);
        }
        if (++buf == NBUF_G)  buf = 0;
        if (++nbuf == NBUF_G) nbuf = 0;
    }

    const int er = lane >> 2;
    const int ec = (lane & 3) * 2;
#pragma unroll
    for (int mt = 0; mt < 2; mt++) {
        const int row0 = bm + wm * 32 + mt * 16 + er;
#pragma unroll
        for (int nt = 0; nt < 4; nt++) {
            const int col = bn + wn * 32 + nt * 8 + ec;
            const float bx = bias[col], by = bias[col + 1];
            float v0 = acc[mt][nt][0] + bx, v1 = acc[mt][nt][1] + by;
            float v2 = acc[mt][nt][2] + bx, v3 = acc[mt][nt][3] + by;
            if (OUTMODE == 0) {
                *(float2*)(Cf + (size_t)row0 * N + col)       = make_float2(v0, v1);
                *(float2*)(Cf + (size_t)(row0 + 8) * N + col) = make_float2(v2, v3);
            } else {
                uint32_t u;
                pack2(v0, v1, u);
                *(uint32_t*)(Ch + (size_t)row0 * N + col) = u;
                pack2(v2, v3, u);
                *(uint32_t*)(Ch + (size_t)(row0 + 8) * N + col) = u;
            }
        }
    }
}

// ---------------------------------------------------------------------------
// HMMA causal flash attention, single fp16, 2 CTAs/SM.
// CTA: 128 q-rows x (b,h). 8 warps x 16 rows. 64-key blocks, 3-buffer KV ring.
// ---------------------------------------------------------------------------
constexpr int SKA_    = 72;
constexpr int QTILE_E = 128 * SKA_;
constexpr int KTILE_E = 64 * SKA_;
constexpr int ATT_STAGE_E = 2 * KTILE_E;          // K, V
constexpr int NBUF_A  = 3;
constexpr int ATT_SMEM = (QTILE_E + NBUF_A * ATT_STAGE_E) * 2;  // 73728 B

__device__ __forceinline__ void stage_kv(uint32_t sbuf,
    const __half* qv, size_t bbase, int colK, int colV, int j0, int tid)
{
#pragma unroll
    for (int it = 0; it < 2; it++) {
        int s   = tid + it * 256;
        int row = s >> 3;
        int ch  = (s & 7) * 8;
        size_t g = bbase + (size_t)(j0 + row) * C3_;
        uint32_t so = (row * SKA_ + ch) * 2;
        cp_async16(sbuf + 0 * KTILE_E * 2 + so, qv + g + colK + ch);
        cp_async16(sbuf + 1 * KTILE_E * 2 + so, qv + g + colV + ch);
    }
}

__global__ __launch_bounds__(256, 2)
void attn_mma(const __half* __restrict__ qv, __half* __restrict__ y)
{
    extern __shared__ __align__(128) __half asm_[];
    const int tid  = threadIdx.x;
    const int wid  = tid >> 5;
    const int lane = tid & 31;
    const int qb = (int)gridDim.x - 1 - (int)blockIdx.x;
    const int bh = blockIdx.y;
    const int b  = bh >> 4;
    const int h  = bh & 15;
    const int q0 = qb * 128;
    const size_t bbase = (size_t)b * T_ * C3_;
    const int colQ = h * D_, colK = C_ + h * D_, colV = 2 * C_ + h * D_;

    const uint32_t sQ  = smem_u32(asm_);
    const uint32_t sSt = sQ + QTILE_E * 2;

    const int nb = 2 * qb + 2;

#pragma unroll
    for (int it = 0; it < 4; it++) {
        int s   = tid + it * 256;
        int row = s >> 3;
        int ch  = (s & 7) * 8;
        size_t g = bbase + (size_t)(q0 + row) * C3_ + colQ + ch;
        cp_async16(sQ + (row * SKA_ + ch) * 2, qv + g);
    }
    stage_kv(sSt, qv, bbase, colK, colV, 0, tid);
    cp_commit();
    if (1 < nb) stage_kv(sSt + ATT_STAGE_E * 2, qv, bbase, colK, colV, 64, tid);
    cp_commit();

    uint32_t aq[4][4];
    float oc[8][4];
#pragma unroll
    for (int i = 0; i < 8; i++)
#pragma unroll
        for (int j = 0; j < 4; j++) oc[i][j] = 0.f;
    float mrow[2] = { -1e30f, -1e30f };
    float lrow[2] = { 0.f, 0.f };

    const float scl = 0.125f * 1.4426950408889634f;
    const int wrow0 = q0 + 16 * wid;

    int buf = 0, nbufi = 2;
    for (int j = 0; j < nb; j++) {
        cp_wait<1>();
        __syncthreads();

        if (j == 0) {
#pragma unroll
            for (int kc = 0; kc < 4; kc++) {
                uint32_t ra = (((16 * wid) + (lane & 15)) * SKA_
                               + (lane >> 4) * 8 + kc * 16) * 2;
                ldsm_x4(aq[kc][0], aq[kc][1], aq[kc][2], aq[kc][3], sQ + ra);
            }
        }

        if (j + 2 < nb)
            stage_kv(sSt + nbufi * ATT_STAGE_E * 2, qv,
                     bbase, colK, colV, (j + 2) * 64, tid);
        cp_commit();

        const int j0 = j * 64;
        if (j0 <= wrow0 + 15) {
            const uint32_t sK = sSt + buf * ATT_STAGE_E * 2;
            const uint32_t sV = sK + KTILE_E * 2;

            float sc[8][4];
#pragma unroll
            for (int i = 0; i < 8; i++)
#pragma unroll
                for (int e = 0; e < 4; e++) sc[i][e] = 0.f;

            const int kb_r = ((lane >> 4) & 1) * 8 + (lane & 7);
            const int kb_c = ((lane >> 3) & 1) * 8;
#pragma unroll
            for (int kc = 0; kc < 4; kc++) {
                uint32_t kb[4][4];
#pragma unroll
                for (int g = 0; g < 4; g++) {
                    uint32_t off = ((g * 16 + kb_r) * SKA_ + kb_c + kc * 16) * 2;
                    ldsm_x4(kb[g][0], kb[g][1], kb[g][2], kb[g][3], sK + off);
                }
#pragma unroll
                for (int nt = 0; nt < 8; nt++)
                    mma16816(sc[nt], aq[kc], &kb[nt >> 1][(nt & 1) * 2]);
            }

            const bool anymask = (j0 + 63 > wrow0);
            const int r0g = wrow0 + (lane >> 2);
#pragma unroll
            for (int nt = 0; nt < 8; nt++)
#pragma unroll
                for (int e = 0; e < 4; e++) {
                    float v = sc[nt][e] * scl;
                    if (anymask) {
                        int key = j0 + nt * 8 + (lane & 3) * 2 + (e & 1);
                        int row = r0g + (e >> 1) * 8;
                        if (key > row) v = -1e30f;
                    }
                    sc[nt][e] = v;
                }

#pragma unroll
            for (int rr = 0; rr < 2; rr++) {
                float mx = -1e30f;
#pragma unroll
                for (int nt = 0; nt < 8; nt++)
                    mx = fmaxf(mx, fmaxf(sc[nt][2 * rr], sc[nt][2 * rr + 1]));
                mx = fmaxf(mx, __shfl_xor_sync(0xffffffffu, mx, 1));
                mx = fmaxf(mx, __shfl_xor_sync(0xffffffffu, mx, 2));
                float mnew = fmaxf(mrow[rr], mx);
                float al   = exp2f(mrow[rr] - mnew);
                mrow[rr] = mnew;
                float rs = 0.f;
#pragma unroll
                for (int nt = 0; nt < 8; nt++) {
                    float p0 = exp2f(sc[nt][2 * rr]     - mnew);
                    float p1 = exp2f(sc[nt][2 * rr + 1] - mnew);
                    sc[nt][2 * rr] = p0; sc[nt][2 * rr + 1] = p1;
                    rs += p0 + p1;
                }
                rs += __shfl_xor_sync(0xffffffffu, rs, 1);
                rs += __shfl_xor_sync(0xffffffffu, rs, 2);
                lrow[rr] = lrow[rr] * al + rs;
#pragma unroll
                for (int nd = 0; nd < 8; nd++) {
                    oc[nd][2 * rr]     *= al;
                    oc[nd][2 * rr + 1] *= al;
                }
            }

#pragma unroll
            for (int t = 0; t < 4; t++) {
                uint32_t ph[4];
                pack2(sc[2 * t][0],     sc[2 * t][1],     ph[0]);
                pack2(sc[2 * t][2],     sc[2 * t][3],     ph[1]);
                pack2(sc[2 * t + 1][0], sc[2 * t + 1][1], ph[2]);
                pack2(sc[2 * t + 1][2], sc[2 * t + 1][3], ph[3]);
                const int vkey = 16 * t + ((lane >> 3) & 1) * 8 + (lane & 7);
                const int vcb  = (lane >> 4) * 8;
#pragma unroll
                for (int nd2 = 0; nd2 < 4; nd2++) {
                    uint32_t vf[4];
                    uint32_t off = (vkey * SKA_ + nd2 * 16 + vcb) * 2;
                    ldsm_x4_t(vf[0], vf[1], vf[2], vf[3], sV + off);
                    mma16816(oc[2 * nd2],     ph, &vf[0]);
                    mma16816(oc[2 * nd2 + 1], ph, &vf[2]);
                }
            }
        }
        if (++buf == NBUF_A)   buf = 0;
        if (++nbufi == NBUF_A) nbufi = 0;
    }

    const float inv0 = 1.0f / lrow[0];
    const float inv1 = 1.0f / lrow[1];
    const int gr0 = wrow0 + (lane >> 2);
    const int gr1 = gr0 + 8;
    const int colb = h * D_ + (lane & 3) * 2;
#pragma unroll
    for (int nd = 0; nd < 8; nd++) {
        const int col = colb + nd * 8;
        uint32_t u;
        pack2(oc[nd][0] * inv0, oc[nd][1] * inv0, u);
        *(uint32_t*)(y + ((size_t)b * T_ + gr0) * C_ + col) = u;
        pack2(oc[nd][2] * inv1, oc[nd][3] * inv1, u);
        *(uint32_t*)(y + ((size_t)b * T_ + gr1) * C_ + col) = u;
    }
}

// ---------------------------------------------------------------------------
extern "C" void kernel_launch(void* const* d_in, const int* in_sizes, int n_in,
                              void* d_out, int out_size)
{
    const float* x      = (const float*)d_in[0];
    const float* w_attn = (const float*)d_in[1];
    const float* b_attn = (const float*)d_in[2];
    const float* w_proj = (const float*)d_in[3];
    const float* b_proj = (const float*)d_in[4];
    float* out = (float*)d_out;

    __half *xc, *wa, *wp, *qk, *yb;
    cudaGetSymbolAddress((void**)&xc, g_x);
    cudaGetSymbolAddress((void**)&wa, g_wa);
    cudaGetSymbolAddress((void**)&wp, g_wp);
    cudaGetSymbolAddress((void**)&qk, g_qkv);
    cudaGetSymbolAddress((void**)&yb, g_y);

    cudaFuncSetAttribute(gemm_mma<0>, cudaFuncAttributeMaxDynamicSharedMemorySize, GEMM_SMEM);
    cudaFuncSetAttribute(gemm_mma<1>, cudaFuncAttributeMaxDynamicSharedMemorySize, GEMM_SMEM);
    cudaFuncSetAttribute(attn_mma,    cudaFuncAttributeMaxDynamicSharedMemorySize, ATT_SMEM);

    // Convert operands to fp16
    {
        int n4;
        n4 = M_ * C_ / 4;   conv_fp16<<<(n4 + 255) / 256, 256>>>(x,      xc, n4);
        n4 = C3_ * C_ / 4;  conv_fp16<<<(n4 + 255) / 256, 256>>>(w_attn, wa, n4);
        n4 = C_ * C_ / 4;   conv_fp16<<<(n4 + 255) / 256, 256>>>(w_proj, wp, n4);
    }

    // 1) QKV projection -> fp16 qkv
    {
        dim3 grid(C3_ / 128, M_ / 128);
        gemm_mma<1><<<grid, 512, GEMM_SMEM>>>(xc, wa, b_attn, nullptr, qk,
                                              M_, C3_, C_);
    }

    // 2) HMMA causal flash attention -> fp16 y
    {
        dim3 grid(T_ / 128, B_ * H_);
        attn_mma<<<grid, 256, ATT_SMEM>>>(qk, yb);
    }

    // 3) Output projection -> fp32 out
    {
        dim3 grid(C_ / 128, M_ / 128);
        gemm_mma<0><<<grid, 512, GEMM_SMEM>>>(yb, wp, b_proj, out, nullptr,
                                              M_, C_, C_);
    }
}

// round 11
// speedup vs baseline: 2.5098x; 1.0879x over previous
#include <cuda_runtime.h>
#include <cuda_fp16.h>
#include <cstdint>

// Problem constants
constexpr int B_  = 2;
constexpr int T_  = 2048;
constexpr int C_  = 1024;
constexpr int H_  = 16;
constexpr int D_  = 64;
constexpr int C3_ = 3 * C_;   // 3072
constexpr int M_  = B_ * T_;  // 4096

// Scratch (allocation-free rule: __device__ globals). Single fp16 everywhere.
__device__ __half g_x  [(size_t)M_  * C_];
__device__ __half g_wa [(size_t)C3_ * C_];
__device__ __half g_wp [(size_t)C_  * C_];
__device__ __half g_qkv[(size_t)M_  * C3_];
__device__ __half g_y  [(size_t)M_  * C_];

// ---------------------------------------------------------------------------
// Baseline-PTX helpers (sm_80+ only)
// ---------------------------------------------------------------------------
__device__ __forceinline__ uint32_t smem_u32(const void* p) {
    uint32_t a;
    asm("{ .reg .u64 t; cvta.to.shared.u64 t, %1; cvt.u32.u64 %0, t; }"
        : "=r"(a) : "l"(p));
    return a;
}
__device__ __forceinline__ void cp_async16(uint32_t saddr, const void* gaddr) {
    asm volatile("cp.async.cg.shared.global [%0], [%1], 16;"
                 :: "r"(saddr), "l"(gaddr) : "memory");
}
__device__ __forceinline__ void cp_commit() {
    asm volatile("cp.async.commit_group;" ::: "memory");
}
template <int N>
__device__ __forceinline__ void cp_wait() {
    asm volatile("cp.async.wait_group %0;" :: "n"(N) : "memory");
}
__device__ __forceinline__ void ldsm_x4(uint32_t& r0, uint32_t& r1,
                                        uint32_t& r2, uint32_t& r3, uint32_t addr) {
    asm volatile("ldmatrix.sync.aligned.m8n8.x4.shared.b16 {%0,%1,%2,%3}, [%4];"
                 : "=r"(r0), "=r"(r1), "=r"(r2), "=r"(r3) : "r"(addr));
}
__device__ __forceinline__ void ldsm_x4_t(uint32_t& r0, uint32_t& r1,
                                          uint32_t& r2, uint32_t& r3, uint32_t addr) {
    asm volatile("ldmatrix.sync.aligned.m8n8.x4.trans.shared.b16 {%0,%1,%2,%3}, [%4];"
                 : "=r"(r0), "=r"(r1), "=r"(r2), "=r"(r3) : "r"(addr));
}
// fp16 inputs, fp32 accumulate
__device__ __forceinline__ void mma16816(float* d, const uint32_t* a, const uint32_t* b) {
    asm volatile(
        "mma.sync.aligned.m16n8k16.row.col.f32.f16.f16.f32 "
        "{%0,%1,%2,%3}, {%4,%5,%6,%7}, {%8,%9}, {%0,%1,%2,%3};"
        : "+f"(d[0]), "+f"(d[1]), "+f"(d[2]), "+f"(d[3])
        : "r"(a[0]), "r"(a[1]), "r"(a[2]), "r"(a[3]), "r"(b[0]), "r"(b[1]));
}
__device__ __forceinline__ void pack2(float v0, float v1, uint32_t& u) {
    __half2 H(__float2half_rn(v0), __float2half_rn(v1));
    u = *(uint32_t*)&H;
}

// ---------------------------------------------------------------------------
// Fused fp32 -> fp16 convert for all three operand tensors (one launch)
// ---------------------------------------------------------------------------
constexpr int N4_X  = M_  * C_ / 4;   // 1048576
constexpr int N4_WA = C3_ * C_ / 4;   //  786432
constexpr int N4_WP = C_  * C_ / 4;   //  262144

__global__ __launch_bounds__(256)
void conv_all(const float* __restrict__ x, const float* __restrict__ wa_in,
              const float* __restrict__ wp_in, __half* __restrict__ xo,
              __half* __restrict__ wao, __half* __restrict__ wpo)
{
    int i = blockIdx.x * blockDim.x + threadIdx.x;
    const float* src; __half* dst; int idx;
    if (i < N4_X)                 { src = x;     dst = xo;  idx = i; }
    else if (i < N4_X + N4_WA)    { src = wa_in; dst = wao; idx = i - N4_X; }
    else if (i < N4_X + N4_WA + N4_WP) { src = wp_in; dst = wpo; idx = i - N4_X - N4_WA; }
    else return;
    float4 v = ((const float4*)src)[idx];
    uint32_t a, b;
    pack2(v.x, v.y, a);
    pack2(v.z, v.w, b);
    ((uint32_t*)dst)[2 * idx + 0] = a;
    ((uint32_t*)dst)[2 * idx + 1] = b;
}

// ---------------------------------------------------------------------------
// HMMA GEMM (NT): single fp16, 256 threads, 8 warps (2x4), warp tile 64x32,
// BK=32, 4-buffer ring (depth 3), 2 CTAs per SM.
// ---------------------------------------------------------------------------
constexpr int BK_   = 32;
constexpr int SKS_  = 40;                        // halfs per row (80 B)
constexpr int MAT_E = 128 * SKS_;                // 5120 halfs
constexpr int STAGE_E = 2 * MAT_E;               // A, B
constexpr int NBUF_G = 4;
constexpr int GEMM_SMEM = NBUF_G * STAGE_E * 2;  // 81920 B per CTA

__device__ __forceinline__ void stage_loads(uint32_t sbuf,
    const __half* A, const __half* Bm,
    int bm, int bn, int k0, int K, int tid)
{
#pragma unroll
    for (int j = 0; j < 2; j++) {
        int s   = tid + j * 256;           // 0..511
        int row = s >> 2;                  // 0..127
        int cb  = (s & 3) * 8;             // 0,8,16,24
        uint32_t so = (row * SKS_ + cb) * 2;
        cp_async16(sbuf + so,             A  + (size_t)(bm + row) * K + k0 + cb);
        cp_async16(sbuf + MAT_E * 2 + so, Bm + (size_t)(bn + row) * K + k0 + cb);
    }
    cp_commit();
}

template <int OUTMODE>
__global__ __launch_bounds__(256, 2)
void gemm_mma(const __half* __restrict__ A, const __half* __restrict__ Bm,
              const float* __restrict__ bias, float* __restrict__ Cf,
              __half* __restrict__ Ch, int M, int N, int K)
{
    extern __shared__ __align__(128) __half smem[];
    const int tid  = threadIdx.x;
    const int wid  = tid >> 5;        // 0..7
    const int lane = tid & 31;
    const int wm   = wid >> 2;        // 0..1 (64 rows)
    const int wn   = wid & 3;         // 0..3 (32 cols)
    const int bm   = blockIdx.y * 128;
    const int bn   = blockIdx.x * 128;
    const uint32_t sbase = smem_u32(smem);

    float acc[4][4][4];
#pragma unroll
    for (int i = 0; i < 4; i++)
#pragma unroll
        for (int j = 0; j < 4; j++)
#pragma unroll
            for (int r = 0; r < 4; r++) acc[i][j][r] = 0.f;

    const int a_row = wm * 64 + (lane & 15);
    const int a_col = (lane >> 4) * 8;
    const int b_row = wn * 32 + ((lane >> 4) & 1) * 8 + (lane & 7);
    const int b_col = ((lane >> 3) & 1) * 8;

    const int S = K / BK_;   // 32

#pragma unroll
    for (int p = 0; p < 3; p++)
        stage_loads(sbase + p * STAGE_E * 2, A, Bm, bm, bn, p * BK_, K, tid);

    int buf = 0, nbuf = 3;
    for (int s = 0; s < S; s++) {
        cp_wait<2>();
        __syncthreads();

        if (s + 3 < S)
            stage_loads(sbase + nbuf * STAGE_E * 2, A, Bm,
                        bm, bn, (s + 3) * BK_, K, tid);
        else
            cp_commit();

        const uint32_t sA = sbase + buf * STAGE_E * 2;
        const uint32_t sB = sA + MAT_E * 2;

#pragma unroll
        for (int ks = 0; ks < 2; ks++) {
            uint32_t af[4][4], bf[2][4];
            const int ac = a_col + ks * 16;
            const int bc = b_col + ks * 16;
#pragma unroll
            for (int mt = 0; mt < 4; mt++) {
                uint32_t ra = ((a_row + mt * 16) * SKS_ + ac) * 2;
                ldsm_x4(af[mt][0], af[mt][1], af[mt][2], af[mt][3], sA + ra);
            }
#pragma unroll
            for (int np = 0; np < 2; np++) {
                uint32_t rb = ((b_row + np * 16) * SKS_ + bc) * 2;
                ldsm_x4(bf[np][0], bf[np][1], bf[np][2], bf[np][3], sB + rb);
            }
#pragma unroll
            for (int mt = 0; mt < 4; mt++)
#pragma unroll
                for (int nt = 0; nt < 4; nt++)
                    mma16816(acc[mt][nt], af[mt], &bf[nt >> 1][(nt & 1) * 2]);
        }
        if (++buf == NBUF_G)  buf = 0;
        if (++nbuf == NBUF_G) nbuf = 0;
    }

    const int er = lane >> 2;
    const int ec = (lane & 3) * 2;
#pragma unroll
    for (int mt = 0; mt < 4; mt++) {
        const int row0 = bm + wm * 64 + mt * 16 + er;
#pragma unroll
        for (int nt = 0; nt < 4; nt++) {
            const int col = bn + wn * 32 + nt * 8 + ec;
            const float bx = bias[col], by = bias[col + 1];
            float v0 = acc[mt][nt][0] + bx, v1 = acc[mt][nt][1] + by;
            float v2 = acc[mt][nt][2] + bx, v3 = acc[mt][nt][3] + by;
            if (OUTMODE == 0) {
                *(float2*)(Cf + (size_t)row0 * N + col)       = make_float2(v0, v1);
                *(float2*)(Cf + (size_t)(row0 + 8) * N + col) = make_float2(v2, v3);
            } else {
                uint32_t u;
                pack2(v0, v1, u);
                *(uint32_t*)(Ch + (size_t)row0 * N + col) = u;
                pack2(v2, v3, u);
                *(uint32_t*)(Ch + (size_t)(row0 + 8) * N + col) = u;
            }
        }
    }
}

// ---------------------------------------------------------------------------
// HMMA causal flash attention, single fp16, 2 CTAs/SM — unchanged from R10.
// ---------------------------------------------------------------------------
constexpr int SKA_    = 72;
constexpr int QTILE_E = 128 * SKA_;
constexpr int KTILE_E = 64 * SKA_;
constexpr int ATT_STAGE_E = 2 * KTILE_E;
constexpr int NBUF_A  = 3;
constexpr int ATT_SMEM = (QTILE_E + NBUF_A * ATT_STAGE_E) * 2;  // 73728 B

__device__ __forceinline__ void stage_kv(uint32_t sbuf,
    const __half* qv, size_t bbase, int colK, int colV, int j0, int tid)
{
#pragma unroll
    for (int it = 0; it < 2; it++) {
        int s   = tid + it * 256;
        int row = s >> 3;
        int ch  = (s & 7) * 8;
        size_t g = bbase + (size_t)(j0 + row) * C3_;
        uint32_t so = (row * SKA_ + ch) * 2;
        cp_async16(sbuf + 0 * KTILE_E * 2 + so, qv + g + colK + ch);
        cp_async16(sbuf + 1 * KTILE_E * 2 + so, qv + g + colV + ch);
    }
}

__global__ __launch_bounds__(256, 2)
void attn_mma(const __half* __restrict__ qv, __half* __restrict__ y)
{
    extern __shared__ __align__(128) __half asm_[];
    const int tid  = threadIdx.x;
    const int wid  = tid >> 5;
    const int lane = tid & 31;
    const int qb = (int)gridDim.x - 1 - (int)blockIdx.x;
    const int bh = blockIdx.y;
    const int b  = bh >> 4;
    const int h  = bh & 15;
    const int q0 = qb * 128;
    const size_t bbase = (size_t)b * T_ * C3_;
    const int colQ = h * D_, colK = C_ + h * D_, colV = 2 * C_ + h * D_;

    const uint32_t sQ  = smem_u32(asm_);
    const uint32_t sSt = sQ + QTILE_E * 2;

    const int nb = 2 * qb + 2;

#pragma unroll
    for (int it = 0; it < 4; it++) {
        int s   = tid + it * 256;
        int row = s >> 3;
        int ch  = (s & 7) * 8;
        size_t g = bbase + (size_t)(q0 + row) * C3_ + colQ + ch;
        cp_async16(sQ + (row * SKA_ + ch) * 2, qv + g);
    }
    stage_kv(sSt, qv, bbase, colK, colV, 0, tid);
    cp_commit();
    if (1 < nb) stage_kv(sSt + ATT_STAGE_E * 2, qv, bbase, colK, colV, 64, tid);
    cp_commit();

    uint32_t aq[4][4];
    float oc[8][4];
#pragma unroll
    for (int i = 0; i < 8; i++)
#pragma unroll
        for (int j = 0; j < 4; j++) oc[i][j] = 0.f;
    float mrow[2] = { -1e30f, -1e30f };
    float lrow[2] = { 0.f, 0.f };

    const float scl = 0.125f * 1.4426950408889634f;
    const int wrow0 = q0 + 16 * wid;

    int buf = 0, nbufi = 2;
    for (int j = 0; j < nb; j++) {
        cp_wait<1>();
        __syncthreads();

        if (j == 0) {
#pragma unroll
            for (int kc = 0; kc < 4; kc++) {
                uint32_t ra = (((16 * wid) + (lane & 15)) * SKA_
                               + (lane >> 4) * 8 + kc * 16) * 2;
                ldsm_x4(aq[kc][0], aq[kc][1], aq[kc][2], aq[kc][3], sQ + ra);
            }
        }

        if (j + 2 < nb)
            stage_kv(sSt + nbufi * ATT_STAGE_E * 2, qv,
                     bbase, colK, colV, (j + 2) * 64, tid);
        cp_commit();

        const int j0 = j * 64;
        if (j0 <= wrow0 + 15) {
            const uint32_t sK = sSt + buf * ATT_STAGE_E * 2;
            const uint32_t sV = sK + KTILE_E * 2;

            float sc[8][4];
#pragma unroll
            for (int i = 0; i < 8; i++)
#pragma unroll
                for (int e = 0; e < 4; e++) sc[i][e] = 0.f;

            const int kb_r = ((lane >> 4) & 1) * 8 + (lane & 7);
            const int kb_c = ((lane >> 3) & 1) * 8;
#pragma unroll
            for (int kc = 0; kc < 4; kc++) {
                uint32_t kb[4][4];
#pragma unroll
                for (int g = 0; g < 4; g++) {
                    uint32_t off = ((g * 16 + kb_r) * SKA_ + kb_c + kc * 16) * 2;
                    ldsm_x4(kb[g][0], kb[g][1], kb[g][2], kb[g][3], sK + off);
                }
#pragma unroll
                for (int nt = 0; nt < 8; nt++)
                    mma16816(sc[nt], aq[kc], &kb[nt >> 1][(nt & 1) * 2]);
            }

            const bool anymask = (j0 + 63 > wrow0);
            const int r0g = wrow0 + (lane >> 2);
#pragma unroll
            for (int nt = 0; nt < 8; nt++)
#pragma unroll
                for (int e = 0; e < 4; e++) {
                    float v = sc[nt][e] * scl;
                    if (anymask) {
                        int key = j0 + nt * 8 + (lane & 3) * 2 + (e & 1);
                        int row = r0g + (e >> 1) * 8;
                        if (key > row) v = -1e30f;
                    }
                    sc[nt][e] = v;
                }

#pragma unroll
            for (int rr = 0; rr < 2; rr++) {
                float mx = -1e30f;
#pragma unroll
                for (int nt = 0; nt < 8; nt++)
                    mx = fmaxf(mx, fmaxf(sc[nt][2 * rr], sc[nt][2 * rr + 1]));
                mx = fmaxf(mx, __shfl_xor_sync(0xffffffffu, mx, 1));
                mx = fmaxf(mx, __shfl_xor_sync(0xffffffffu, mx, 2));
                float mnew = fmaxf(mrow[rr], mx);
                float al   = exp2f(mrow[rr] - mnew);
                mrow[rr] = mnew;
                float rs = 0.f;
#pragma unroll
                for (int nt = 0; nt < 8; nt++) {
                    float p0 = exp2f(sc[nt][2 * rr]     - mnew);
                    float p1 = exp2f(sc[nt][2 * rr + 1] - mnew);
                    sc[nt][2 * rr] = p0; sc[nt][2 * rr + 1] = p1;
                    rs += p0 + p1;
                }
                rs += __shfl_xor_sync(0xffffffffu, rs, 1);
                rs += __shfl_xor_sync(0xffffffffu, rs, 2);
                lrow[rr] = lrow[rr] * al + rs;
#pragma unroll
                for (int nd = 0; nd < 8; nd++) {
                    oc[nd][2 * rr]     *= al;
                    oc[nd][2 * rr + 1] *= al;
                }
            }

#pragma unroll
            for (int t = 0; t < 4; t++) {
                uint32_t ph[4];
                pack2(sc[2 * t][0],     sc[2 * t][1],     ph[0]);
                pack2(sc[2 * t][2],     sc[2 * t][3],     ph[1]);
                pack2(sc[2 * t + 1][0], sc[2 * t + 1][1], ph[2]);
                pack2(sc[2 * t + 1][2], sc[2 * t + 1][3], ph[3]);
                const int vkey = 16 * t + ((lane >> 3) & 1) * 8 + (lane & 7);
                const int vcb  = (lane >> 4) * 8;
#pragma unroll
                for (int nd2 = 0; nd2 < 4; nd2++) {
                    uint32_t vf[4];
                    uint32_t off = (vkey * SKA_ + nd2 * 16 + vcb) * 2;
                    ldsm_x4_t(vf[0], vf[1], vf[2], vf[3], sV + off);
                    mma16816(oc[2 * nd2],     ph, &vf[0]);
                    mma16816(oc[2 * nd2 + 1], ph, &vf[2]);
                }
            }
        }
        if (++buf == NBUF_A)   buf = 0;
        if (++nbufi == NBUF_A) nbufi = 0;
    }

    const float inv0 = 1.0f / lrow[0];
    const float inv1 = 1.0f / lrow[1];
    const int gr0 = wrow0 + (lane >> 2);
    const int gr1 = gr0 + 8;
    const int colb = h * D_ + (lane & 3) * 2;
#pragma unroll
    for (int nd = 0; nd < 8; nd++) {
        const int col = colb + nd * 8;
        uint32_t u;
        pack2(oc[nd][0] * inv0, oc[nd][1] * inv0, u);
        *(uint32_t*)(y + ((size_t)b * T_ + gr0) * C_ + col) = u;
        pack2(oc[nd][2] * inv1, oc[nd][3] * inv1, u);
        *(uint32_t*)(y + ((size_t)b * T_ + gr1) * C_ + col) = u;
    }
}

// ---------------------------------------------------------------------------
extern "C" void kernel_launch(void* const* d_in, const int* in_sizes, int n_in,
                              void* d_out, int out_size)
{
    const float* x      = (const float*)d_in[0];
    const float* w_attn = (const float*)d_in[1];
    const float* b_attn = (const float*)d_in[2];
    const float* w_proj = (const float*)d_in[3];
    const float* b_proj = (const float*)d_in[4];
    float* out = (float*)d_out;

    __half *xc, *wa, *wp, *qk, *yb;
    cudaGetSymbolAddress((void**)&xc, g_x);
    cudaGetSymbolAddress((void**)&wa, g_wa);
    cudaGetSymbolAddress((void**)&wp, g_wp);
    cudaGetSymbolAddress((void**)&qk, g_qkv);
    cudaGetSymbolAddress((void**)&yb, g_y);

    cudaFuncSetAttribute(gemm_mma<0>, cudaFuncAttributeMaxDynamicSharedMemorySize, GEMM_SMEM);
    cudaFuncSetAttribute(gemm_mma<1>, cudaFuncAttributeMaxDynamicSharedMemorySize, GEMM_SMEM);
    cudaFuncSetAttribute(attn_mma,    cudaFuncAttributeMaxDynamicSharedMemorySize, ATT_SMEM);

    // Convert all operands to fp16 in one launch
    {
        int total = N4_X + N4_WA + N4_WP;
        conv_all<<<(total + 255) / 256, 256>>>(x, w_attn, w_proj, xc, wa, wp);
    }

    // 1) QKV projection -> fp16 qkv
    {
        dim3 grid(C3_ / 128, M_ / 128);
        gemm_mma<1><<<grid, 256, GEMM_SMEM>>>(xc, wa, b_attn, nullptr, qk,
                                              M_, C3_, C_);
    }

    // 2) HMMA causal flash attention -> fp16 y
    {
        dim3 grid(T_ / 128, B_ * H_);
        attn_mma<<<grid, 256, ATT_SMEM>>>(qk, yb);
    }

    // 3) Output projection -> fp32 out
    {
        dim3 grid(C_ / 128, M_ / 128);
        gemm_mma<0><<<grid, 256, GEMM_SMEM>>>(yb, wp, b_proj, out, nullptr,
                                              M_, C_, C_);
    }
}